// round 12
// baseline (speedup 1.0000x reference)
#include <cuda_runtime.h>
#include <cuda_bf16.h>
#include <cuda_fp16.h>
#include <math.h>
#include <stdint.h>

// Problem constants
#define BATCH 2
#define SEQ   4096
#define DIM   512
#define ROWS  (BATCH * SEQ)          // 8192
#define DD    (DIM * DIM)

typedef __nv_bfloat16 bf16;

// ---------------------------------------------------------------------------
// Device scratch (static globals — no allocations)
// ---------------------------------------------------------------------------
__device__ bf16   g_xh[ROWS * DIM],  g_xl[ROWS * DIM];   // x bf16 split
__device__ __half g_xf[ROWS * DIM];                       // x fp16 (scores B)
__device__ bf16   g_wnh[2 * DD], g_wnl[2 * DD];           // Wq(0), Wk(1) native split
__device__ bf16   g_wvth[DD], g_wvtl[DD];                 // Wv^T split
__device__ float  g_Mt[DD];                               // M^T fp32 accum
__device__ bf16   g_Mth[DD], g_Mtl[DD];                   // M^T bf16 split
__device__ __half g_Yh[ROWS * DIM];                       // y = x·M fp16
__device__ __half g_Vth[(size_t)BATCH * DIM * SEQ];       // V^T fp16 [b][d][s]
__device__ __half g_Ph[(size_t)BATCH * SEQ * SEQ];        // P fp16
__device__ float  g_sum[ROWS];                            // exp row sums (atomic)
__device__ float  g_inv[ROWS];                            // 1/rowsum

// ---------------------------------------------------------------------------
// helpers (baseline sm_80+ PTX only — NO tcgen05 / 'a'-gated features)
// ---------------------------------------------------------------------------
__device__ __forceinline__ uint32_t smem_u32(const void* p) {
    uint32_t a;
    asm("{ .reg .u64 t; cvta.to.shared.u64 t, %1; cvt.u32.u64 %0, t; }" : "=r"(a) : "l"(p));
    return a;
}
#define CP16(dst, src) \
    asm volatile("cp.async.cg.shared.global [%0], [%1], 16;" :: "r"(dst), "l"(src))
#define CP_COMMIT() asm volatile("cp.async.commit_group;" ::: "memory")
#define CP_WAIT2()  asm volatile("cp.async.wait_group 2;" ::: "memory")
#define CP_WAIT1()  asm volatile("cp.async.wait_group 1;" ::: "memory")
#define CP_WAIT0()  asm volatile("cp.async.wait_group 0;" ::: "memory")

__device__ __forceinline__ void ldm_x4(uint32_t* r, uint32_t addr) {
    asm volatile("ldmatrix.sync.aligned.m8n8.x4.shared.b16 {%0,%1,%2,%3}, [%4];"
        : "=r"(r[0]), "=r"(r[1]), "=r"(r[2]), "=r"(r[3]) : "r"(addr));
}
__device__ __forceinline__ void mma_bf16(float* c, const uint32_t* a, const uint32_t* b) {
    asm volatile(
        "mma.sync.aligned.m16n8k16.row.col.f32.bf16.bf16.f32 "
        "{%0,%1,%2,%3}, {%4,%5,%6,%7}, {%8,%9}, {%0,%1,%2,%3};"
        : "+f"(c[0]), "+f"(c[1]), "+f"(c[2]), "+f"(c[3])
        : "r"(a[0]), "r"(a[1]), "r"(a[2]), "r"(a[3]), "r"(b[0]), "r"(b[1]));
}
__device__ __forceinline__ void mma_f16(float* c, const uint32_t* a, const uint32_t* b) {
    asm volatile(
        "mma.sync.aligned.m16n8k16.row.col.f32.f16.f16.f32 "
        "{%0,%1,%2,%3}, {%4,%5,%6,%7}, {%8,%9}, {%0,%1,%2,%3};"
        : "+f"(c[0]), "+f"(c[1]), "+f"(c[2]), "+f"(c[3])
        : "r"(a[0]), "r"(a[1]), "r"(a[2]), "r"(a[3]), "r"(b[0]), "r"(b[1]));
}
__device__ __forceinline__ void store2_h(__half* o, float a, float b) {
    *(__half2*)o = __halves2half2(__float2half_rn(a), __float2half_rn(b));
}

// smem: per-array 128 rows x 80 bytes (proven conflict-free layout)
#define ARR   10240

// ---------------------------------------------------------------------------
// NT GEMM via mma.sync: C[128x128] = sum_k A[m,k]*B[n,k], KC=32.
// MODE 5 (bf16 3-term, 2-stage, 2 CTA/SM): M^T = Wk·Wq^T, split-K over z,
//        fp32 atomicAdd into outF [512,512].
// MODE 0 (bf16 3-term, 2-stage, 2 CTA/SM): projections.
//        z=0 -> y (outH fp16): A=x split, B=M^T split
//        z=1 -> V^T (outH3 fp16, [b][d][s]): A=Wv^T split (Ch/Cl), B=x split
// MODE 4 (fp16 1-term, 3-stage, 3 CTA/SM): scores, exp + atomic row sums
// MODE 1 (fp16 1-term, 3-stage, 3 CTA/SM): context, outF = val * rowscale
// ---------------------------------------------------------------------------
template <int MODE>
__global__ __launch_bounds__(256, (MODE == 0 || MODE == 5) ? 2 : 3)
void mma_gemm(const uint16_t* __restrict__ Ah, const uint16_t* __restrict__ Al,
              const uint16_t* __restrict__ Bh, const uint16_t* __restrict__ Bl,
              const uint16_t* __restrict__ Ch, const uint16_t* __restrict__ Cl,
              int K, int ld, size_t strideA, size_t strideB,
              float alpha, const float* __restrict__ rowscale, float* gsum,
              float* __restrict__ outF, size_t strideOut, int ldOut,
              __half* __restrict__ outH, __half* __restrict__ outH3)
{
    constexpr bool T3   = (MODE == 0 || MODE == 5);   // 3-term bf16 split
    constexpr int  NARR = T3 ? 4 : 2;
    constexpr int  STG  = NARR * ARR;
    constexpr int  OFFB = T3 ? 2 * ARR : ARR;         // Bh offset within stage

    extern __shared__ char smem[];
    const uint32_t sb = smem_u32(smem);
    const int tid  = threadIdx.x;
    const int lane = tid & 31;
    const int wid  = tid >> 5;
    const int wm   = wid & 1;         // 2 warps along M (64 rows each)
    const int wn   = wid >> 1;        // 4 warps along N (32 cols each)
    const int z  = blockIdx.z;

    int m0, n0;
    const uint16_t *aH, *aL = nullptr, *bH, *bL = nullptr;
    if (MODE == 5) {                  // split-K: z selects K window
        m0 = blockIdx.y * 128;
        n0 = blockIdx.x * 128;
        const int koff = z * 64;
        aH = Ah + (size_t)m0 * ld + koff;
        aL = Al + (size_t)m0 * ld + koff;
        bH = Bh + (size_t)n0 * ld + koff;
        bL = Bl + (size_t)n0 * ld + koff;
    } else if (MODE == 0) {
        if (z == 0) {      // y: m over ROWS (bx), n over DIM (by)
            m0 = blockIdx.x * 128;
            n0 = blockIdx.y * 128;
            aH = Ah + (size_t)m0 * ld;          // x hi
            aL = Al + (size_t)m0 * ld;          // x lo
            bH = Bh + (size_t)n0 * ld;          // M^T hi
            bL = Bl + (size_t)n0 * ld;          // M^T lo
        } else {           // V: m over DIM (by), n over ROWS (bx)
            m0 = blockIdx.y * 128;
            n0 = blockIdx.x * 128;
            aH = Ch + (size_t)m0 * ld;          // Wv^T hi
            aL = Cl + (size_t)m0 * ld;          // Wv^T lo
            bH = Ah + (size_t)n0 * ld;          // x hi
            bL = Al + (size_t)n0 * ld;          // x lo
        }
    } else {
        m0 = blockIdx.y * 128;
        n0 = blockIdx.x * 128;
        aH = Ah + z * strideA + (size_t)m0 * ld;
        bH = Bh + z * strideB + (size_t)n0 * ld;
    }

    float acc[4][4][4];
#pragma unroll
    for (int i = 0; i < 4; i++)
#pragma unroll
        for (int j = 0; j < 4; j++)
#pragma unroll
            for (int q = 0; q < 4; q++) acc[i][j][q] = 0.f;

    const int nc = K >> 5;   // 32-wide k chunks

    auto load_stage = [&](int s, int k0) {
        const uint32_t base = sb + s * STG;
#pragma unroll
        for (int i = 0; i < 2; i++) {
            const int c   = tid + i * 256;
            const int row = c >> 2, kc = c & 3;
            const uint32_t doff = (uint32_t)(row * 80 + kc * 16);
            const size_t   soff = (size_t)row * ld + k0 + kc * 8;
            CP16(base + doff, (const void*)(aH + soff));
            CP16(base + OFFB + doff, (const void*)(bH + soff));
            if (T3) {
                CP16(base + 1 * ARR + doff, (const void*)(aL + soff));
                CP16(base + 3 * ARR + doff, (const void*)(bL + soff));
            }
        }
    };

    load_stage(0, 0);
    CP_COMMIT();
    if (!T3) { load_stage(1, 32); CP_COMMIT(); }

    for (int c = 0; c < nc; c++) {
        if (T3) {
            if (c + 1 < nc) {
                load_stage((c + 1) & 1, (c + 1) << 5);
                CP_COMMIT();
                CP_WAIT1();
            } else {
                CP_WAIT0();
            }
        } else {
            if (c + 2 < nc) { load_stage((c + 2) % 3, (c + 2) << 5); CP_COMMIT(); }
            if      (c + 2 < nc) CP_WAIT2();
            else if (c + 1 < nc) CP_WAIT1();
            else                 CP_WAIT0();
        }
        __syncthreads();

        const uint32_t s0 = sb + (T3 ? (c & 1) : (c % 3)) * STG;
#pragma unroll
        for (int ks = 0; ks < 2; ks++) {
            uint32_t ah[4][4], al[4][4];
#pragma unroll
            for (int mi = 0; mi < 4; mi++) {
                const uint32_t ad = s0 +
                    (uint32_t)((wm * 64 + mi * 16 + (lane & 15)) * 80 + ks * 32 + (lane >> 4) * 16);
                ldm_x4(ah[mi], ad);
                if (T3) ldm_x4(al[mi], ad + ARR);
            }
#pragma unroll
            for (int bi = 0; bi < 2; bi++) {
                const uint32_t bd = s0 + OFFB +
                    (uint32_t)((wn * 32 + bi * 16 + (lane & 15)) * 80 + ks * 32 + (lane >> 4) * 16);
                uint32_t bh[4], bl[4];
                ldm_x4(bh, bd);
                if (T3) ldm_x4(bl, bd + ARR);
#pragma unroll
                for (int n2 = 0; n2 < 2; n2++) {
                    const int ni = bi * 2 + n2;
                    uint32_t bbh[2] = { bh[n2], bh[2 + n2] };
                    if (T3) {
                        uint32_t bbl[2] = { bl[n2], bl[2 + n2] };
#pragma unroll
                        for (int mi = 0; mi < 4; mi++) mma_bf16(acc[mi][ni], ah[mi], bbh);  // hh
#pragma unroll
                        for (int mi = 0; mi < 4; mi++) mma_bf16(acc[mi][ni], al[mi], bbh);  // lh
#pragma unroll
                        for (int mi = 0; mi < 4; mi++) mma_bf16(acc[mi][ni], ah[mi], bbl);  // hl
                    } else {
#pragma unroll
                        for (int mi = 0; mi < 4; mi++) mma_f16(acc[mi][ni], ah[mi], bbh);   // hh
                    }
                }
            }
        }
        __syncthreads();
    }

    // ---- epilogue ----
    const int r  = lane >> 2;
    const int cq = (lane & 3) * 2;
#pragma unroll
    for (int mi = 0; mi < 4; mi++) {
        const int row0 = m0 + wm * 64 + mi * 16 + r;   // second half: row0+8
        float rs0 = 0.f, rs1 = 0.f;
#pragma unroll
        for (int ni = 0; ni < 4; ni++) {
            const int col = n0 + wn * 32 + ni * 8 + cq;
            float v00 = acc[mi][ni][0], v01 = acc[mi][ni][1];
            float v10 = acc[mi][ni][2], v11 = acc[mi][ni][3];
            if (MODE == 5) {           // split-K accumulate into M^T fp32
                atomicAdd(&outF[(size_t)row0 * DIM + col],     v00);
                atomicAdd(&outF[(size_t)row0 * DIM + col + 1], v01);
                atomicAdd(&outF[(size_t)(row0 + 8) * DIM + col],     v10);
                atomicAdd(&outF[(size_t)(row0 + 8) * DIM + col + 1], v11);
            } else if (MODE == 0) {
                if (z == 0) {
                    const size_t o0 = (size_t)row0 * ldOut + col;
                    const size_t o1 = (size_t)(row0 + 8) * ldOut + col;
                    store2_h(outH + o0, v00, v01);
                    store2_h(outH + o1, v10, v11);
                } else {   // V^T: rows=d, cols=(b,s)
                    const int b = col >> 12, s = col & 4095;
                    const size_t o0 = (size_t)b * DIM * SEQ + (size_t)row0 * SEQ + s;
                    const size_t o1 = o0 + (size_t)8 * SEQ;
                    store2_h(outH3 + o0, v00, v01);
                    store2_h(outH3 + o1, v10, v11);
                }
            } else if (MODE == 4) {    // scores: exp + fp16 + row sums
                float e00 = __expf(v00 * alpha), e01 = __expf(v01 * alpha);
                float e10 = __expf(v10 * alpha), e11 = __expf(v11 * alpha);
                rs0 += e00 + e01;
                rs1 += e10 + e11;
                const size_t base = (size_t)z * SEQ * SEQ;
                const size_t o0 = base + (size_t)row0 * SEQ + col;
                const size_t o1 = base + (size_t)(row0 + 8) * SEQ + col;
                store2_h(outH + o0, e00, e01);
                store2_h(outH + o1, e10, e11);
            } else {                   // MODE 1: context, normalized fp32 out
                const float s0 = rowscale[z * SEQ + row0];
                const float s1 = rowscale[z * SEQ + row0 + 8];
                float* o0 = outF + z * strideOut + (size_t)row0 * ldOut + col;
                float* o1 = outF + z * strideOut + (size_t)(row0 + 8) * ldOut + col;
                *(float2*)o0 = make_float2(v00 * s0, v01 * s0);
                *(float2*)o1 = make_float2(v10 * s1, v11 * s1);
            }
        }
        if (MODE == 4) {
            rs0 += __shfl_xor_sync(0xffffffffu, rs0, 1);
            rs0 += __shfl_xor_sync(0xffffffffu, rs0, 2);
            rs1 += __shfl_xor_sync(0xffffffffu, rs1, 1);
            rs1 += __shfl_xor_sync(0xffffffffu, rs1, 2);
            if ((lane & 3) == 0) {
                atomicAdd(&gsum[z * SEQ + row0], rs0);
                atomicAdd(&gsum[z * SEQ + row0 + 8], rs1);
            }
        }
    }
}

// ---------------------------------------------------------------------------
// prep kernels
// ---------------------------------------------------------------------------
// zero M^T accumulator + row sums
__global__ void zero_scratch(float* __restrict__ Mt, float* __restrict__ s)
{
    int i = blockIdx.x * blockDim.x + threadIdx.x;
    if (i < DD) Mt[i] = 0.f;
    else if (i < DD + ROWS) s[i - DD] = 0.f;
}

// x -> bf16 split (hi/lo) + fp16 copy
__global__ void split_x(const float* __restrict__ in, bf16* __restrict__ h,
                        bf16* __restrict__ l, __half* __restrict__ f, int n4)
{
    int i = blockIdx.x * blockDim.x + threadIdx.x;
    if (i >= n4) return;
    float4 v = ((const float4*)in)[i];
    bf16 h0 = __float2bfloat16(v.x), h1 = __float2bfloat16(v.y);
    bf16 h2 = __float2bfloat16(v.z), h3 = __float2bfloat16(v.w);
    __nv_bfloat162 hp0, hp1, lp0, lp1;
    hp0.x = h0; hp0.y = h1; hp1.x = h2; hp1.y = h3;
    lp0.x = __float2bfloat16(v.x - __bfloat162float(h0));
    lp0.y = __float2bfloat16(v.y - __bfloat162float(h1));
    lp1.x = __float2bfloat16(v.z - __bfloat162float(h2));
    lp1.y = __float2bfloat16(v.w - __bfloat162float(h3));
    ((__nv_bfloat162*)h)[i * 2 + 0] = hp0;
    ((__nv_bfloat162*)h)[i * 2 + 1] = hp1;
    ((__nv_bfloat162*)l)[i * 2 + 0] = lp0;
    ((__nv_bfloat162*)l)[i * 2 + 1] = lp1;
    ((__half2*)f)[i * 2 + 0] = __halves2half2(__float2half_rn(v.x), __float2half_rn(v.y));
    ((__half2*)f)[i * 2 + 1] = __halves2half2(__float2half_rn(v.z), __float2half_rn(v.w));
}

// ALL weight prep in one launch: z=0/1 -> Wq/Wk native split, z=2 -> Wv^T split
__global__ void prep_w(const float* __restrict__ Wq, const float* __restrict__ Wk,
                       const float* __restrict__ Wv,
                       bf16* __restrict__ wnh, bf16* __restrict__ wnl,
                       bf16* __restrict__ wvth, bf16* __restrict__ wvtl)
{
    int id = blockIdx.x * blockDim.x + threadIdx.x;
    int z  = blockIdx.y;
    if (id >= DD) return;
    if (z < 2) {
        float v = (z == 0) ? Wq[id] : Wk[id];
        bf16 hh = __float2bfloat16(v);
        wnh[(size_t)z * DD + id] = hh;
        wnl[(size_t)z * DD + id] = __float2bfloat16(v - __bfloat162float(hh));
    } else {
        int k = id >> 9, n = id & 511;
        float v = Wv[id];
        bf16 hh = __float2bfloat16(v);
        wvth[n * DIM + k] = hh;
        wvtl[n * DIM + k] = __float2bfloat16(v - __bfloat162float(hh));
    }
}

// M^T fp32 -> bf16 split
__global__ void split_M(const float* __restrict__ Mt, bf16* __restrict__ h,
                        bf16* __restrict__ l)
{
    int i = blockIdx.x * blockDim.x + threadIdx.x;
    if (i >= DD) return;
    float v = Mt[i];
    bf16 hh = __float2bfloat16(v);
    h[i] = hh;
    l[i] = __float2bfloat16(v - __bfloat162float(hh));
}

__global__ void invert_sums(const float* __restrict__ s, float* __restrict__ inv)
{
    int i = blockIdx.x * blockDim.x + threadIdx.x;
    if (i < ROWS) inv[i] = 1.0f / s[i];
}

// ---------------------------------------------------------------------------
extern "C" void kernel_launch(void* const* d_in, const int* in_sizes, int n_in,
                              void* d_out, int out_size)
{
    const float* x  = (const float*)d_in[0];
    const float* Wq = (const float*)d_in[1];
    const float* Wk = (const float*)d_in[2];
    const float* Wv = (const float*)d_in[3];
    float* out = (float*)d_out;

    bf16 *xh, *xl, *wnh, *wnl, *wvth, *wvtl, *Mth, *Mtl;
    __half *xf, *Yh, *Vth, *Ph;
    float *Mt, *sum, *inv;
    cudaGetSymbolAddress((void**)&xh,   g_xh);   cudaGetSymbolAddress((void**)&xl,   g_xl);
    cudaGetSymbolAddress((void**)&xf,   g_xf);
    cudaGetSymbolAddress((void**)&wnh,  g_wnh);  cudaGetSymbolAddress((void**)&wnl,  g_wnl);
    cudaGetSymbolAddress((void**)&wvth, g_wvth); cudaGetSymbolAddress((void**)&wvtl, g_wvtl);
    cudaGetSymbolAddress((void**)&Mt,   g_Mt);
    cudaGetSymbolAddress((void**)&Mth,  g_Mth);  cudaGetSymbolAddress((void**)&Mtl,  g_Mtl);
    cudaGetSymbolAddress((void**)&Yh,   g_Yh);
    cudaGetSymbolAddress((void**)&Vth,  g_Vth);
    cudaGetSymbolAddress((void**)&Ph,   g_Ph);
    cudaGetSymbolAddress((void**)&sum,  g_sum);
    cudaGetSymbolAddress((void**)&inv,  g_inv);

    const int SMEM3 = 2 * 4 * ARR;   // 3-term, 2 stages (81920)
    const int SMEM1 = 3 * 2 * ARR;   // 1-term, 3 stages (61440)
    cudaFuncSetAttribute(mma_gemm<5>, cudaFuncAttributeMaxDynamicSharedMemorySize, SMEM3);
    cudaFuncSetAttribute(mma_gemm<0>, cudaFuncAttributeMaxDynamicSharedMemorySize, SMEM3);
    cudaFuncSetAttribute(mma_gemm<4>, cudaFuncAttributeMaxDynamicSharedMemorySize, SMEM1);
    cudaFuncSetAttribute(mma_gemm<1>, cudaFuncAttributeMaxDynamicSharedMemorySize, SMEM1);

    const float inv_sqrt_d = 0.04419417382415922f;  // 1/sqrt(512)

    // 0) prep: zero (M^T + sums), split x, all weight prep in one launch
    zero_scratch<<<(DD + ROWS + 255) / 256, 256>>>(Mt, sum);
    split_x<<<(ROWS * DIM / 4 + 255) / 256, 256>>>(x, xh, xl, xf, ROWS * DIM / 4);
    {
        dim3 g((DD + 255) / 256, 3);
        prep_w<<<g, 256>>>(Wq, Wk, Wv, wnh, wnl, wvth, wvtl);
    }

    // 1) M^T = Wk · Wq^T, split-K over 8 (K=64 each), fp32 atomic accumulate
    {
        dim3 g(4, 4, 8);
        mma_gemm<5><<<g, 256, SMEM3>>>(
            (const uint16_t*)(wnh + DD), (const uint16_t*)(wnl + DD),  // A = Wk
            (const uint16_t*)wnh, (const uint16_t*)wnl,                 // B = Wq
            nullptr, nullptr,
            64, DIM, 0, 0,
            1.f, nullptr, nullptr, Mt, 0, DIM, nullptr, nullptr);
    }
    split_M<<<(DD + 255) / 256, 256>>>(Mt, Mth, Mtl);

    // 2) projections: z=0 -> y = x·M^T^T (fp16), z=1 -> V^T (fp16)
    {
        dim3 g(ROWS / 128, DIM / 128, 2);   // (64, 4, 2)
        mma_gemm<0><<<g, 256, SMEM3>>>(
            (const uint16_t*)xh, (const uint16_t*)xl,
            (const uint16_t*)Mth, (const uint16_t*)Mtl,
            (const uint16_t*)wvth, (const uint16_t*)wvtl,
            DIM, DIM, 0, 0,
            1.f, nullptr, nullptr, nullptr, 0, DIM, Yh, Vth);
    }

    // 3) fused scores + softmax-exp: P = exp(y·x^T/sqrt(d))  (fp16 1-term, 3 CTA/SM)
    {
        dim3 g(SEQ / 128, SEQ / 128, BATCH);
        mma_gemm<4><<<g, 256, SMEM1>>>(
            (const uint16_t*)Yh, nullptr, (const uint16_t*)xf, nullptr,
            nullptr, nullptr,
            DIM, DIM, (size_t)SEQ * DIM, (size_t)SEQ * DIM,
            inv_sqrt_d, nullptr, sum, nullptr, 0, 0, Ph, nullptr);
    }

    // 4) invert row sums
    invert_sums<<<(ROWS + 255) / 256, 256>>>(sum, inv);

    // 5) context = diag(1/rowsum) * (P @ V)  (fp16 1-term, 3 CTA/SM, B = V^T)
    {
        dim3 g(DIM / 128, SEQ / 128, BATCH);
        mma_gemm<1><<<g, 256, SMEM1>>>(
            (const uint16_t*)Ph, nullptr, (const uint16_t*)Vth, nullptr,
            nullptr, nullptr,
            SEQ, SEQ, (size_t)SEQ * SEQ, (size_t)DIM * SEQ,
            1.f, inv, nullptr, out, (size_t)SEQ * DIM, DIM, nullptr, nullptr);
    }
}

// round 14
// speedup vs baseline: 1.2736x; 1.2736x over previous
#include <cuda_runtime.h>
#include <cuda_bf16.h>
#include <cuda_fp16.h>
#include <math.h>
#include <stdint.h>

// Problem constants
#define BATCH 2
#define SEQ   4096
#define DIM   512
#define ROWS  (BATCH * SEQ)          // 8192
#define DD    (DIM * DIM)

typedef __nv_bfloat16 bf16;

// ---------------------------------------------------------------------------
// Device scratch (static globals — no allocations)
// ---------------------------------------------------------------------------
__device__ bf16   g_xh[ROWS * DIM],  g_xl[ROWS * DIM];   // x bf16 split
__device__ __half g_xf[ROWS * DIM];                       // x fp16 (scores B)
__device__ bf16   g_wnh[2 * DD], g_wnl[2 * DD];           // Wq(0), Wk(1) native split
__device__ bf16   g_wvth[DD], g_wvtl[DD];                 // Wv^T split
__device__ float  g_Mt[DD];                               // M^T fp32 accum
__device__ bf16   g_Mth[DD], g_Mtl[DD];                   // M^T bf16 split
__device__ __half g_Yh[ROWS * DIM];                       // y = x·M fp16
__device__ __half g_Vth[(size_t)BATCH * DIM * SEQ];       // V^T fp16 [b][d][s]
__device__ __half g_Ph[(size_t)BATCH * SEQ * SEQ];        // P fp16
__device__ float  g_sum[ROWS];                            // exp row sums (atomic)
__device__ float  g_inv[ROWS];                            // 1/rowsum

// ---------------------------------------------------------------------------
// helpers (baseline sm_80+ PTX only — NO tcgen05 / 'a'-gated features)
// ---------------------------------------------------------------------------
__device__ __forceinline__ uint32_t smem_u32(const void* p) {
    uint32_t a;
    asm("{ .reg .u64 t; cvta.to.shared.u64 t, %1; cvt.u32.u64 %0, t; }" : "=r"(a) : "l"(p));
    return a;
}
#define CP16(dst, src) \
    asm volatile("cp.async.cg.shared.global [%0], [%1], 16;" :: "r"(dst), "l"(src))
#define CP_COMMIT() asm volatile("cp.async.commit_group;" ::: "memory")
#define CP_WAIT2()  asm volatile("cp.async.wait_group 2;" ::: "memory")
#define CP_WAIT1()  asm volatile("cp.async.wait_group 1;" ::: "memory")
#define CP_WAIT0()  asm volatile("cp.async.wait_group 0;" ::: "memory")

__device__ __forceinline__ void ldm_x4(uint32_t* r, uint32_t addr) {
    asm volatile("ldmatrix.sync.aligned.m8n8.x4.shared.b16 {%0,%1,%2,%3}, [%4];"
        : "=r"(r[0]), "=r"(r[1]), "=r"(r[2]), "=r"(r[3]) : "r"(addr));
}
__device__ __forceinline__ void mma_bf16(float* c, const uint32_t* a, const uint32_t* b) {
    asm volatile(
        "mma.sync.aligned.m16n8k16.row.col.f32.bf16.bf16.f32 "
        "{%0,%1,%2,%3}, {%4,%5,%6,%7}, {%8,%9}, {%0,%1,%2,%3};"
        : "+f"(c[0]), "+f"(c[1]), "+f"(c[2]), "+f"(c[3])
        : "r"(a[0]), "r"(a[1]), "r"(a[2]), "r"(a[3]), "r"(b[0]), "r"(b[1]));
}
__device__ __forceinline__ void mma_f16(float* c, const uint32_t* a, const uint32_t* b) {
    asm volatile(
        "mma.sync.aligned.m16n8k16.row.col.f32.f16.f16.f32 "
        "{%0,%1,%2,%3}, {%4,%5,%6,%7}, {%8,%9}, {%0,%1,%2,%3};"
        : "+f"(c[0]), "+f"(c[1]), "+f"(c[2]), "+f"(c[3])
        : "r"(a[0]), "r"(a[1]), "r"(a[2]), "r"(a[3]), "r"(b[0]), "r"(b[1]));
}
__device__ __forceinline__ void store2_h(__half* o, float a, float b) {
    *(__half2*)o = __halves2half2(__float2half_rn(a), __float2half_rn(b));
}

// smem: per-array 128 rows x 80 bytes (proven conflict-free layout)
#define ARR   10240

// ---------------------------------------------------------------------------
// NT GEMM via mma.sync: C[128x128] = sum_k A[m,k]*B[n,k], KC=32.
// ALL modes: __launch_bounds__(256, 2) — 128 regs/thread is a hard floor
// for the 64-accumulator tile (R12 lesson: (256,3) spills and regresses).
// MODE 5 (bf16 3-term, 2-stage): M^T = Wk·Wq^T, split-K over z,
//        fp32 atomicAdd into outF [512,512].
// MODE 0 (bf16 3-term, 2-stage): projections.
//        z=0 -> y (outH fp16): A=x split, B=M^T split
//        z=1 -> V^T (outH3 fp16, [b][d][s]): A=Wv^T split (Ch/Cl), B=x split
// MODE 4 (fp16 1-term, 3-stage): scores, exp + atomic row sums
// MODE 1 (fp16 1-term, 3-stage): context, outF = val * rowscale
// ---------------------------------------------------------------------------
template <int MODE>
__global__ __launch_bounds__(256, 2)
void mma_gemm(const uint16_t* __restrict__ Ah, const uint16_t* __restrict__ Al,
              const uint16_t* __restrict__ Bh, const uint16_t* __restrict__ Bl,
              const uint16_t* __restrict__ Ch, const uint16_t* __restrict__ Cl,
              int K, int ld, size_t strideA, size_t strideB,
              float alpha, const float* __restrict__ rowscale, float* gsum,
              float* __restrict__ outF, size_t strideOut, int ldOut,
              __half* __restrict__ outH, __half* __restrict__ outH3)
{
    constexpr bool T3   = (MODE == 0 || MODE == 5);   // 3-term bf16 split
    constexpr int  NARR = T3 ? 4 : 2;
    constexpr int  STG  = NARR * ARR;
    constexpr int  OFFB = T3 ? 2 * ARR : ARR;         // Bh offset within stage

    extern __shared__ char smem[];
    const uint32_t sb = smem_u32(smem);
    const int tid  = threadIdx.x;
    const int lane = tid & 31;
    const int wid  = tid >> 5;
    const int wm   = wid & 1;         // 2 warps along M (64 rows each)
    const int wn   = wid >> 1;        // 4 warps along N (32 cols each)
    const int z  = blockIdx.z;

    int m0, n0;
    const uint16_t *aH, *aL = nullptr, *bH, *bL = nullptr;
    if (MODE == 5) {                  // split-K: z selects K window
        m0 = blockIdx.y * 128;
        n0 = blockIdx.x * 128;
        const int koff = z * 64;
        aH = Ah + (size_t)m0 * ld + koff;
        aL = Al + (size_t)m0 * ld + koff;
        bH = Bh + (size_t)n0 * ld + koff;
        bL = Bl + (size_t)n0 * ld + koff;
    } else if (MODE == 0) {
        if (z == 0) {      // y: m over ROWS (bx), n over DIM (by)
            m0 = blockIdx.x * 128;
            n0 = blockIdx.y * 128;
            aH = Ah + (size_t)m0 * ld;          // x hi
            aL = Al + (size_t)m0 * ld;          // x lo
            bH = Bh + (size_t)n0 * ld;          // M^T hi
            bL = Bl + (size_t)n0 * ld;          // M^T lo
        } else {           // V: m over DIM (by), n over ROWS (bx)
            m0 = blockIdx.y * 128;
            n0 = blockIdx.x * 128;
            aH = Ch + (size_t)m0 * ld;          // Wv^T hi
            aL = Cl + (size_t)m0 * ld;          // Wv^T lo
            bH = Ah + (size_t)n0 * ld;          // x hi
            bL = Al + (size_t)n0 * ld;          // x lo
        }
    } else {
        m0 = blockIdx.y * 128;
        n0 = blockIdx.x * 128;
        aH = Ah + z * strideA + (size_t)m0 * ld;
        bH = Bh + z * strideB + (size_t)n0 * ld;
    }

    float acc[4][4][4];
#pragma unroll
    for (int i = 0; i < 4; i++)
#pragma unroll
        for (int j = 0; j < 4; j++)
#pragma unroll
            for (int q = 0; q < 4; q++) acc[i][j][q] = 0.f;

    const int nc = K >> 5;   // 32-wide k chunks

    auto load_stage = [&](int s, int k0) {
        const uint32_t base = sb + s * STG;
#pragma unroll
        for (int i = 0; i < 2; i++) {
            const int c   = tid + i * 256;
            const int row = c >> 2, kc = c & 3;
            const uint32_t doff = (uint32_t)(row * 80 + kc * 16);
            const size_t   soff = (size_t)row * ld + k0 + kc * 8;
            CP16(base + doff, (const void*)(aH + soff));
            CP16(base + OFFB + doff, (const void*)(bH + soff));
            if (T3) {
                CP16(base + 1 * ARR + doff, (const void*)(aL + soff));
                CP16(base + 3 * ARR + doff, (const void*)(bL + soff));
            }
        }
    };

    load_stage(0, 0);
    CP_COMMIT();
    if (!T3) { load_stage(1, 32); CP_COMMIT(); }

    for (int c = 0; c < nc; c++) {
        if (T3) {
            if (c + 1 < nc) {
                load_stage((c + 1) & 1, (c + 1) << 5);
                CP_COMMIT();
                CP_WAIT1();
            } else {
                CP_WAIT0();
            }
        } else {
            if (c + 2 < nc) { load_stage((c + 2) % 3, (c + 2) << 5); CP_COMMIT(); }
            if      (c + 2 < nc) CP_WAIT2();
            else if (c + 1 < nc) CP_WAIT1();
            else                 CP_WAIT0();
        }
        __syncthreads();

        const uint32_t s0 = sb + (T3 ? (c & 1) : (c % 3)) * STG;
#pragma unroll
        for (int ks = 0; ks < 2; ks++) {
            uint32_t ah[4][4], al[4][4];
#pragma unroll
            for (int mi = 0; mi < 4; mi++) {
                const uint32_t ad = s0 +
                    (uint32_t)((wm * 64 + mi * 16 + (lane & 15)) * 80 + ks * 32 + (lane >> 4) * 16);
                ldm_x4(ah[mi], ad);
                if (T3) ldm_x4(al[mi], ad + ARR);
            }
#pragma unroll
            for (int bi = 0; bi < 2; bi++) {
                const uint32_t bd = s0 + OFFB +
                    (uint32_t)((wn * 32 + bi * 16 + (lane & 15)) * 80 + ks * 32 + (lane >> 4) * 16);
                uint32_t bh[4], bl[4];
                ldm_x4(bh, bd);
                if (T3) ldm_x4(bl, bd + ARR);
#pragma unroll
                for (int n2 = 0; n2 < 2; n2++) {
                    const int ni = bi * 2 + n2;
                    uint32_t bbh[2] = { bh[n2], bh[2 + n2] };
                    if (T3) {
                        uint32_t bbl[2] = { bl[n2], bl[2 + n2] };
#pragma unroll
                        for (int mi = 0; mi < 4; mi++) mma_bf16(acc[mi][ni], ah[mi], bbh);  // hh
#pragma unroll
                        for (int mi = 0; mi < 4; mi++) mma_bf16(acc[mi][ni], al[mi], bbh);  // lh
#pragma unroll
                        for (int mi = 0; mi < 4; mi++) mma_bf16(acc[mi][ni], ah[mi], bbl);  // hl
                    } else {
#pragma unroll
                        for (int mi = 0; mi < 4; mi++) mma_f16(acc[mi][ni], ah[mi], bbh);   // hh
                    }
                }
            }
        }
        __syncthreads();
    }

    // ---- epilogue ----
    const int r  = lane >> 2;
    const int cq = (lane & 3) * 2;
#pragma unroll
    for (int mi = 0; mi < 4; mi++) {
        const int row0 = m0 + wm * 64 + mi * 16 + r;   // second half: row0+8
        float rs0 = 0.f, rs1 = 0.f;
#pragma unroll
        for (int ni = 0; ni < 4; ni++) {
            const int col = n0 + wn * 32 + ni * 8 + cq;
            float v00 = acc[mi][ni][0], v01 = acc[mi][ni][1];
            float v10 = acc[mi][ni][2], v11 = acc[mi][ni][3];
            if (MODE == 5) {           // split-K accumulate into M^T fp32
                atomicAdd(&outF[(size_t)row0 * DIM + col],     v00);
                atomicAdd(&outF[(size_t)row0 * DIM + col + 1], v01);
                atomicAdd(&outF[(size_t)(row0 + 8) * DIM + col],     v10);
                atomicAdd(&outF[(size_t)(row0 + 8) * DIM + col + 1], v11);
            } else if (MODE == 0) {
                if (z == 0) {
                    const size_t o0 = (size_t)row0 * ldOut + col;
                    const size_t o1 = (size_t)(row0 + 8) * ldOut + col;
                    store2_h(outH + o0, v00, v01);
                    store2_h(outH + o1, v10, v11);
                } else {   // V^T: rows=d, cols=(b,s)
                    const int b = col >> 12, s = col & 4095;
                    const size_t o0 = (size_t)b * DIM * SEQ + (size_t)row0 * SEQ + s;
                    const size_t o1 = o0 + (size_t)8 * SEQ;
                    store2_h(outH3 + o0, v00, v01);
                    store2_h(outH3 + o1, v10, v11);
                }
            } else if (MODE == 4) {    // scores: exp + fp16 + row sums
                float e00 = __expf(v00 * alpha), e01 = __expf(v01 * alpha);
                float e10 = __expf(v10 * alpha), e11 = __expf(v11 * alpha);
                rs0 += e00 + e01;
                rs1 += e10 + e11;
                const size_t base = (size_t)z * SEQ * SEQ;
                const size_t o0 = base + (size_t)row0 * SEQ + col;
                const size_t o1 = base + (size_t)(row0 + 8) * SEQ + col;
                store2_h(outH + o0, e00, e01);
                store2_h(outH + o1, e10, e11);
            } else {                   // MODE 1: context, normalized fp32 out
                const float s0 = rowscale[z * SEQ + row0];
                const float s1 = rowscale[z * SEQ + row0 + 8];
                float* o0 = outF + z * strideOut + (size_t)row0 * ldOut + col;
                float* o1 = outF + z * strideOut + (size_t)(row0 + 8) * ldOut + col;
                *(float2*)o0 = make_float2(v00 * s0, v01 * s0);
                *(float2*)o1 = make_float2(v10 * s1, v11 * s1);
            }
        }
        if (MODE == 4) {
            rs0 += __shfl_xor_sync(0xffffffffu, rs0, 1);
            rs0 += __shfl_xor_sync(0xffffffffu, rs0, 2);
            rs1 += __shfl_xor_sync(0xffffffffu, rs1, 1);
            rs1 += __shfl_xor_sync(0xffffffffu, rs1, 2);
            if ((lane & 3) == 0) {
                atomicAdd(&gsum[z * SEQ + row0], rs0);
                atomicAdd(&gsum[z * SEQ + row0 + 8], rs1);
            }
        }
    }
}

// ---------------------------------------------------------------------------
// prep kernels
// ---------------------------------------------------------------------------
// zero M^T accumulator + row sums
__global__ void zero_scratch(float* __restrict__ Mt, float* __restrict__ s)
{
    int i = blockIdx.x * blockDim.x + threadIdx.x;
    if (i < DD) Mt[i] = 0.f;
    else if (i < DD + ROWS) s[i - DD] = 0.f;
}

// x -> bf16 split (hi/lo) + fp16 copy
__global__ void split_x(const float* __restrict__ in, bf16* __restrict__ h,
                        bf16* __restrict__ l, __half* __restrict__ f, int n4)
{
    int i = blockIdx.x * blockDim.x + threadIdx.x;
    if (i >= n4) return;
    float4 v = ((const float4*)in)[i];
    bf16 h0 = __float2bfloat16(v.x), h1 = __float2bfloat16(v.y);
    bf16 h2 = __float2bfloat16(v.z), h3 = __float2bfloat16(v.w);
    __nv_bfloat162 hp0, hp1, lp0, lp1;
    hp0.x = h0; hp0.y = h1; hp1.x = h2; hp1.y = h3;
    lp0.x = __float2bfloat16(v.x - __bfloat162float(h0));
    lp0.y = __float2bfloat16(v.y - __bfloat162float(h1));
    lp1.x = __float2bfloat16(v.z - __bfloat162float(h2));
    lp1.y = __float2bfloat16(v.w - __bfloat162float(h3));
    ((__nv_bfloat162*)h)[i * 2 + 0] = hp0;
    ((__nv_bfloat162*)h)[i * 2 + 1] = hp1;
    ((__nv_bfloat162*)l)[i * 2 + 0] = lp0;
    ((__nv_bfloat162*)l)[i * 2 + 1] = lp1;
    ((__half2*)f)[i * 2 + 0] = __halves2half2(__float2half_rn(v.x), __float2half_rn(v.y));
    ((__half2*)f)[i * 2 + 1] = __halves2half2(__float2half_rn(v.z), __float2half_rn(v.w));
}

// ALL weight prep in one launch: z=0/1 -> Wq/Wk native split, z=2 -> Wv^T split
__global__ void prep_w(const float* __restrict__ Wq, const float* __restrict__ Wk,
                       const float* __restrict__ Wv,
                       bf16* __restrict__ wnh, bf16* __restrict__ wnl,
                       bf16* __restrict__ wvth, bf16* __restrict__ wvtl)
{
    int id = blockIdx.x * blockDim.x + threadIdx.x;
    int z  = blockIdx.y;
    if (id >= DD) return;
    if (z < 2) {
        float v = (z == 0) ? Wq[id] : Wk[id];
        bf16 hh = __float2bfloat16(v);
        wnh[(size_t)z * DD + id] = hh;
        wnl[(size_t)z * DD + id] = __float2bfloat16(v - __bfloat162float(hh));
    } else {
        int k = id >> 9, n = id & 511;
        float v = Wv[id];
        bf16 hh = __float2bfloat16(v);
        wvth[n * DIM + k] = hh;
        wvtl[n * DIM + k] = __float2bfloat16(v - __bfloat162float(hh));
    }
}

// M^T fp32 -> bf16 split
__global__ void split_M(const float* __restrict__ Mt, bf16* __restrict__ h,
                        bf16* __restrict__ l)
{
    int i = blockIdx.x * blockDim.x + threadIdx.x;
    if (i >= DD) return;
    float v = Mt[i];
    bf16 hh = __float2bfloat16(v);
    h[i] = hh;
    l[i] = __float2bfloat16(v - __bfloat162float(hh));
}

__global__ void invert_sums(const float* __restrict__ s, float* __restrict__ inv)
{
    int i = blockIdx.x * blockDim.x + threadIdx.x;
    if (i < ROWS) inv[i] = 1.0f / s[i];
}

// ---------------------------------------------------------------------------
extern "C" void kernel_launch(void* const* d_in, const int* in_sizes, int n_in,
                              void* d_out, int out_size)
{
    const float* x  = (const float*)d_in[0];
    const float* Wq = (const float*)d_in[1];
    const float* Wk = (const float*)d_in[2];
    const float* Wv = (const float*)d_in[3];
    float* out = (float*)d_out;

    bf16 *xh, *xl, *wnh, *wnl, *wvth, *wvtl, *Mth, *Mtl;
    __half *xf, *Yh, *Vth, *Ph;
    float *Mt, *sum, *inv;
    cudaGetSymbolAddress((void**)&xh,   g_xh);   cudaGetSymbolAddress((void**)&xl,   g_xl);
    cudaGetSymbolAddress((void**)&xf,   g_xf);
    cudaGetSymbolAddress((void**)&wnh,  g_wnh);  cudaGetSymbolAddress((void**)&wnl,  g_wnl);
    cudaGetSymbolAddress((void**)&wvth, g_wvth); cudaGetSymbolAddress((void**)&wvtl, g_wvtl);
    cudaGetSymbolAddress((void**)&Mt,   g_Mt);
    cudaGetSymbolAddress((void**)&Mth,  g_Mth);  cudaGetSymbolAddress((void**)&Mtl,  g_Mtl);
    cudaGetSymbolAddress((void**)&Yh,   g_Yh);
    cudaGetSymbolAddress((void**)&Vth,  g_Vth);
    cudaGetSymbolAddress((void**)&Ph,   g_Ph);
    cudaGetSymbolAddress((void**)&sum,  g_sum);
    cudaGetSymbolAddress((void**)&inv,  g_inv);

    const int SMEM3 = 2 * 4 * ARR;   // 3-term, 2 stages (81920)
    const int SMEM1 = 3 * 2 * ARR;   // 1-term, 3 stages (61440)
    cudaFuncSetAttribute(mma_gemm<5>, cudaFuncAttributeMaxDynamicSharedMemorySize, SMEM3);
    cudaFuncSetAttribute(mma_gemm<0>, cudaFuncAttributeMaxDynamicSharedMemorySize, SMEM3);
    cudaFuncSetAttribute(mma_gemm<4>, cudaFuncAttributeMaxDynamicSharedMemorySize, SMEM1);
    cudaFuncSetAttribute(mma_gemm<1>, cudaFuncAttributeMaxDynamicSharedMemorySize, SMEM1);

    const float inv_sqrt_d = 0.04419417382415922f;  // 1/sqrt(512)

    // 0) prep: zero (M^T + sums), split x, all weight prep in one launch
    zero_scratch<<<(DD + ROWS + 255) / 256, 256>>>(Mt, sum);
    split_x<<<(ROWS * DIM / 4 + 255) / 256, 256>>>(x, xh, xl, xf, ROWS * DIM / 4);
    {
        dim3 g((DD + 255) / 256, 3);
        prep_w<<<g, 256>>>(Wq, Wk, Wv, wnh, wnl, wvth, wvtl);
    }

    // 1) M^T = Wk · Wq^T, split-K over 8 (K=64 each), fp32 atomic accumulate
    {
        dim3 g(4, 4, 8);
        mma_gemm<5><<<g, 256, SMEM3>>>(
            (const uint16_t*)(wnh + DD), (const uint16_t*)(wnl + DD),  // A = Wk
            (const uint16_t*)wnh, (const uint16_t*)wnl,                 // B = Wq
            nullptr, nullptr,
            64, DIM, 0, 0,
            1.f, nullptr, nullptr, Mt, 0, DIM, nullptr, nullptr);
    }
    split_M<<<(DD + 255) / 256, 256>>>(Mt, Mth, Mtl);

    // 2) projections: z=0 -> y = x·M^T^T (fp16), z=1 -> V^T (fp16)
    {
        dim3 g(ROWS / 128, DIM / 128, 2);   // (64, 4, 2)
        mma_gemm<0><<<g, 256, SMEM3>>>(
            (const uint16_t*)xh, (const uint16_t*)xl,
            (const uint16_t*)Mth, (const uint16_t*)Mtl,
            (const uint16_t*)wvth, (const uint16_t*)wvtl,
            DIM, DIM, 0, 0,
            1.f, nullptr, nullptr, nullptr, 0, DIM, Yh, Vth);
    }

    // 3) fused scores + softmax-exp: P = exp(y·x^T/sqrt(d))  (fp16 1-term)
    {
        dim3 g(SEQ / 128, SEQ / 128, BATCH);
        mma_gemm<4><<<g, 256, SMEM1>>>(
            (const uint16_t*)Yh, nullptr, (const uint16_t*)xf, nullptr,
            nullptr, nullptr,
            DIM, DIM, (size_t)SEQ * DIM, (size_t)SEQ * DIM,
            inv_sqrt_d, nullptr, sum, nullptr, 0, 0, Ph, nullptr);
    }

    // 4) invert row sums
    invert_sums<<<(ROWS + 255) / 256, 256>>>(sum, inv);

    // 5) context = diag(1/rowsum) * (P @ V)  (fp16 1-term, B = V^T)
    {
        dim3 g(DIM / 128, SEQ / 128, BATCH);
        mma_gemm<1><<<g, 256, SMEM1>>>(
            (const uint16_t*)Ph, nullptr, (const uint16_t*)Vth, nullptr,
            nullptr, nullptr,
            SEQ, SEQ, (size_t)SEQ * SEQ, (size_t)DIM * SEQ,
            1.f, inv, nullptr, out, (size_t)SEQ * DIM, DIM, nullptr, nullptr);
    }
}

// round 15
// speedup vs baseline: 1.2931x; 1.0153x over previous
#include <cuda_runtime.h>
#include <cuda_bf16.h>
#include <cuda_fp16.h>
#include <math.h>
#include <stdint.h>

// Problem constants
#define BATCH 2
#define SEQ   4096
#define DIM   512
#define ROWS  (BATCH * SEQ)          // 8192
#define DD    (DIM * DIM)

typedef __nv_bfloat16 bf16;

// ---------------------------------------------------------------------------
// Device scratch (static globals — no allocations)
// ---------------------------------------------------------------------------
__device__ bf16   g_xh[ROWS * DIM],  g_xl[ROWS * DIM];   // x bf16 split
__device__ __half g_xf[ROWS * DIM];                       // x fp16 (scores B)
__device__ bf16   g_wnh[2 * DD], g_wnl[2 * DD];           // Wq(0), Wk(1) native split
__device__ bf16   g_wvth[DD], g_wvtl[DD];                 // Wv^T split
__device__ float  g_Mt[DD];                               // M^T fp32 accum
__device__ bf16   g_Mth[DD], g_Mtl[DD];                   // M^T bf16 split
__device__ __half g_Yh[ROWS * DIM];                       // y = x·M fp16
__device__ __half g_Vth[(size_t)BATCH * DIM * SEQ];       // V^T fp16 [b][d][s]
__device__ __half g_Ph[(size_t)BATCH * SEQ * SEQ];        // P fp16
__device__ float  g_sum[ROWS];                            // exp row sums (atomic)

// ---------------------------------------------------------------------------
// helpers (baseline sm_80+ PTX only — NO tcgen05 / 'a'-gated features)
// ---------------------------------------------------------------------------
__device__ __forceinline__ uint32_t smem_u32(const void* p) {
    uint32_t a;
    asm("{ .reg .u64 t; cvta.to.shared.u64 t, %1; cvt.u32.u64 %0, t; }" : "=r"(a) : "l"(p));
    return a;
}
#define CP16(dst, src) \
    asm volatile("cp.async.cg.shared.global [%0], [%1], 16;" :: "r"(dst), "l"(src))
#define CP_COMMIT() asm volatile("cp.async.commit_group;" ::: "memory")
#define CP_WAIT1()  asm volatile("cp.async.wait_group 1;" ::: "memory")
#define CP_WAIT0()  asm volatile("cp.async.wait_group 0;" ::: "memory")

__device__ __forceinline__ void ldm_x4(uint32_t* r, uint32_t addr) {
    asm volatile("ldmatrix.sync.aligned.m8n8.x4.shared.b16 {%0,%1,%2,%3}, [%4];"
        : "=r"(r[0]), "=r"(r[1]), "=r"(r[2]), "=r"(r[3]) : "r"(addr));
}
__device__ __forceinline__ void mma_bf16(float* c, const uint32_t* a, const uint32_t* b) {
    asm volatile(
        "mma.sync.aligned.m16n8k16.row.col.f32.bf16.bf16.f32 "
        "{%0,%1,%2,%3}, {%4,%5,%6,%7}, {%8,%9}, {%0,%1,%2,%3};"
        : "+f"(c[0]), "+f"(c[1]), "+f"(c[2]), "+f"(c[3])
        : "r"(a[0]), "r"(a[1]), "r"(a[2]), "r"(a[3]), "r"(b[0]), "r"(b[1]));
}
__device__ __forceinline__ void mma_f16(float* c, const uint32_t* a, const uint32_t* b) {
    asm volatile(
        "mma.sync.aligned.m16n8k16.row.col.f32.f16.f16.f32 "
        "{%0,%1,%2,%3}, {%4,%5,%6,%7}, {%8,%9}, {%0,%1,%2,%3};"
        : "+f"(c[0]), "+f"(c[1]), "+f"(c[2]), "+f"(c[3])
        : "r"(a[0]), "r"(a[1]), "r"(a[2]), "r"(a[3]), "r"(b[0]), "r"(b[1]));
}
__device__ __forceinline__ void store2_h(__half* o, float a, float b) {
    *(__half2*)o = __halves2half2(__float2half_rn(a), __float2half_rn(b));
}

// smem: per-array 128 rows x 80 bytes (proven conflict-free layout)
#define ARR   10240

// ---------------------------------------------------------------------------
// NT GEMM via mma.sync: C[128x128] = sum_k A[m,k]*B[n,k], KC=32.
// ALL modes: __launch_bounds__(256, 2) — 128 regs/thread is a hard floor
// for the 64-accumulator tile (R12 lesson: (256,3) spills and regresses).
// MODE 5 (bf16 3-term, 2-stage): M^T = Wk·Wq^T, split-K over z,
//        fp32 atomicAdd into outF [512,512].
// MODE 0 (bf16 3-term, 2-stage): projections.
//        z=0 -> y (outH fp16): A=x split, B=M^T split
//        z=1 -> V^T (outH3 fp16, [b][d][s]): A=Wv^T split (Ch/Cl), B=x split
// MODE 4 (fp16 1-term, 3-stage, 1 barrier/chunk): scores, exp + atomic sums
// MODE 1 (fp16 1-term, 3-stage, 1 barrier/chunk): context,
//        outF = val / rowsum[z*SEQ+row]   (invert folded into epilogue)
// ---------------------------------------------------------------------------
template <int MODE>
__global__ __launch_bounds__(256, 2)
void mma_gemm(const uint16_t* __restrict__ Ah, const uint16_t* __restrict__ Al,
              const uint16_t* __restrict__ Bh, const uint16_t* __restrict__ Bl,
              const uint16_t* __restrict__ Ch, const uint16_t* __restrict__ Cl,
              int K, int ld, size_t strideA, size_t strideB,
              float alpha, const float* __restrict__ rowsum, float* gsum,
              float* __restrict__ outF, size_t strideOut, int ldOut,
              __half* __restrict__ outH, __half* __restrict__ outH3)
{
    constexpr bool T3   = (MODE == 0 || MODE == 5);   // 3-term bf16 split
    constexpr int  NARR = T3 ? 4 : 2;
    constexpr int  STG  = NARR * ARR;
    constexpr int  OFFB = T3 ? 2 * ARR : ARR;         // Bh offset within stage

    extern __shared__ char smem[];
    const uint32_t sb = smem_u32(smem);
    const int tid  = threadIdx.x;
    const int lane = tid & 31;
    const int wid  = tid >> 5;
    const int wm   = wid & 1;         // 2 warps along M (64 rows each)
    const int wn   = wid >> 1;        // 4 warps along N (32 cols each)
    const int z  = blockIdx.z;

    int m0, n0;
    const uint16_t *aH, *aL = nullptr, *bH, *bL = nullptr;
    if (MODE == 5) {                  // split-K: z selects K window
        m0 = blockIdx.y * 128;
        n0 = blockIdx.x * 128;
        const int koff = z * 64;
        aH = Ah + (size_t)m0 * ld + koff;
        aL = Al + (size_t)m0 * ld + koff;
        bH = Bh + (size_t)n0 * ld + koff;
        bL = Bl + (size_t)n0 * ld + koff;
    } else if (MODE == 0) {
        if (z == 0) {      // y: m over ROWS (bx), n over DIM (by)
            m0 = blockIdx.x * 128;
            n0 = blockIdx.y * 128;
            aH = Ah + (size_t)m0 * ld;          // x hi
            aL = Al + (size_t)m0 * ld;          // x lo
            bH = Bh + (size_t)n0 * ld;          // M^T hi
            bL = Bl + (size_t)n0 * ld;          // M^T lo
        } else {           // V: m over DIM (by), n over ROWS (bx)
            m0 = blockIdx.y * 128;
            n0 = blockIdx.x * 128;
            aH = Ch + (size_t)m0 * ld;          // Wv^T hi
            aL = Cl + (size_t)m0 * ld;          // Wv^T lo
            bH = Ah + (size_t)n0 * ld;          // x hi
            bL = Al + (size_t)n0 * ld;          // x lo
        }
    } else {
        m0 = blockIdx.y * 128;
        n0 = blockIdx.x * 128;
        aH = Ah + z * strideA + (size_t)m0 * ld;
        bH = Bh + z * strideB + (size_t)n0 * ld;
    }

    float acc[4][4][4];
#pragma unroll
    for (int i = 0; i < 4; i++)
#pragma unroll
        for (int j = 0; j < 4; j++)
#pragma unroll
            for (int q = 0; q < 4; q++) acc[i][j][q] = 0.f;

    const int nc = K >> 5;   // 32-wide k chunks

    auto load_stage = [&](int s, int k0) {
        const uint32_t base = sb + s * STG;
#pragma unroll
        for (int i = 0; i < 2; i++) {
            const int c   = tid + i * 256;
            const int row = c >> 2, kc = c & 3;
            const uint32_t doff = (uint32_t)(row * 80 + kc * 16);
            const size_t   soff = (size_t)row * ld + k0 + kc * 8;
            CP16(base + doff, (const void*)(aH + soff));
            CP16(base + OFFB + doff, (const void*)(bH + soff));
            if (T3) {
                CP16(base + 1 * ARR + doff, (const void*)(aL + soff));
                CP16(base + 3 * ARR + doff, (const void*)(bL + soff));
            }
        }
    };

    auto compute_chunk = [&](uint32_t s0) {
#pragma unroll
        for (int ks = 0; ks < 2; ks++) {
            uint32_t ah[4][4], al[4][4];
#pragma unroll
            for (int mi = 0; mi < 4; mi++) {
                const uint32_t ad = s0 +
                    (uint32_t)((wm * 64 + mi * 16 + (lane & 15)) * 80 + ks * 32 + (lane >> 4) * 16);
                ldm_x4(ah[mi], ad);
                if (T3) ldm_x4(al[mi], ad + ARR);
            }
#pragma unroll
            for (int bi = 0; bi < 2; bi++) {
                const uint32_t bd = s0 + OFFB +
                    (uint32_t)((wn * 32 + bi * 16 + (lane & 15)) * 80 + ks * 32 + (lane >> 4) * 16);
                uint32_t bh[4], bl[4];
                ldm_x4(bh, bd);
                if (T3) ldm_x4(bl, bd + ARR);
#pragma unroll
                for (int n2 = 0; n2 < 2; n2++) {
                    const int ni = bi * 2 + n2;
                    uint32_t bbh[2] = { bh[n2], bh[2 + n2] };
                    if (T3) {
                        uint32_t bbl[2] = { bl[n2], bl[2 + n2] };
#pragma unroll
                        for (int mi = 0; mi < 4; mi++) mma_bf16(acc[mi][ni], ah[mi], bbh);  // hh
#pragma unroll
                        for (int mi = 0; mi < 4; mi++) mma_bf16(acc[mi][ni], al[mi], bbh);  // lh
#pragma unroll
                        for (int mi = 0; mi < 4; mi++) mma_bf16(acc[mi][ni], ah[mi], bbl);  // hl
                    } else {
#pragma unroll
                        for (int mi = 0; mi < 4; mi++) mma_f16(acc[mi][ni], ah[mi], bbh);   // hh
                    }
                }
            }
        }
    };

    if (T3) {
        // 2-stage double buffer: two barriers per chunk (write hits the
        // stage read last iteration — trailing barrier is load-bearing).
        load_stage(0, 0);
        CP_COMMIT();
        for (int c = 0; c < nc; c++) {
            if (c + 1 < nc) {
                load_stage((c + 1) & 1, (c + 1) << 5);
                CP_COMMIT();
                CP_WAIT1();
            } else {
                CP_WAIT0();
            }
            __syncthreads();
            compute_chunk(sb + (c & 1) * STG);
            __syncthreads();
        }
    } else {
        // 3-stage: ONE barrier per chunk. The load for c+2 targets the stage
        // read at c-1; the barrier after the wait proves all warps finished
        // c-1's compute, so issuing the load after it is safe.
        load_stage(0, 0);
        CP_COMMIT();
        load_stage(1, 32);
        CP_COMMIT();
        for (int c = 0; c < nc; c++) {
            if (c + 1 < nc) CP_WAIT1();
            else            CP_WAIT0();
            __syncthreads();
            if (c + 2 < nc) {
                load_stage((c + 2) % 3, (c + 2) << 5);
                CP_COMMIT();
            }
            compute_chunk(sb + (c % 3) * STG);
        }
    }

    // ---- epilogue ----
    const int r  = lane >> 2;
    const int cq = (lane & 3) * 2;
#pragma unroll
    for (int mi = 0; mi < 4; mi++) {
        const int row0 = m0 + wm * 64 + mi * 16 + r;   // second half: row0+8
        float rs0 = 0.f, rs1 = 0.f;
        float is0 = 0.f, is1 = 0.f;
        if (MODE == 1) {               // invert folded here (was its own kernel)
            is0 = 1.0f / rowsum[z * SEQ + row0];
            is1 = 1.0f / rowsum[z * SEQ + row0 + 8];
        }
#pragma unroll
        for (int ni = 0; ni < 4; ni++) {
            const int col = n0 + wn * 32 + ni * 8 + cq;
            float v00 = acc[mi][ni][0], v01 = acc[mi][ni][1];
            float v10 = acc[mi][ni][2], v11 = acc[mi][ni][3];
            if (MODE == 5) {           // split-K accumulate into M^T fp32
                atomicAdd(&outF[(size_t)row0 * DIM + col],     v00);
                atomicAdd(&outF[(size_t)row0 * DIM + col + 1], v01);
                atomicAdd(&outF[(size_t)(row0 + 8) * DIM + col],     v10);
                atomicAdd(&outF[(size_t)(row0 + 8) * DIM + col + 1], v11);
            } else if (MODE == 0) {
                if (z == 0) {
                    const size_t o0 = (size_t)row0 * ldOut + col;
                    const size_t o1 = (size_t)(row0 + 8) * ldOut + col;
                    store2_h(outH + o0, v00, v01);
                    store2_h(outH + o1, v10, v11);
                } else {   // V^T: rows=d, cols=(b,s)
                    const int b = col >> 12, s = col & 4095;
                    const size_t o0 = (size_t)b * DIM * SEQ + (size_t)row0 * SEQ + s;
                    const size_t o1 = o0 + (size_t)8 * SEQ;
                    store2_h(outH3 + o0, v00, v01);
                    store2_h(outH3 + o1, v10, v11);
                }
            } else if (MODE == 4) {    // scores: exp + fp16 + row sums
                float e00 = __expf(v00 * alpha), e01 = __expf(v01 * alpha);
                float e10 = __expf(v10 * alpha), e11 = __expf(v11 * alpha);
                rs0 += e00 + e01;
                rs1 += e10 + e11;
                const size_t base = (size_t)z * SEQ * SEQ;
                const size_t o0 = base + (size_t)row0 * SEQ + col;
                const size_t o1 = base + (size_t)(row0 + 8) * SEQ + col;
                store2_h(outH + o0, e00, e01);
                store2_h(outH + o1, e10, e11);
            } else {                   // MODE 1: context, normalized fp32 out
                float* o0 = outF + z * strideOut + (size_t)row0 * ldOut + col;
                float* o1 = outF + z * strideOut + (size_t)(row0 + 8) * ldOut + col;
                *(float2*)o0 = make_float2(v00 * is0, v01 * is0);
                *(float2*)o1 = make_float2(v10 * is1, v11 * is1);
            }
        }
        if (MODE == 4) {
            rs0 += __shfl_xor_sync(0xffffffffu, rs0, 1);
            rs0 += __shfl_xor_sync(0xffffffffu, rs0, 2);
            rs1 += __shfl_xor_sync(0xffffffffu, rs1, 1);
            rs1 += __shfl_xor_sync(0xffffffffu, rs1, 2);
            if ((lane & 3) == 0) {
                atomicAdd(&gsum[z * SEQ + row0], rs0);
                atomicAdd(&gsum[z * SEQ + row0 + 8], rs1);
            }
        }
    }
}

// ---------------------------------------------------------------------------
// merged prep kernel: blockIdx.y selects the job (all independent)
//   y=0: split x -> bf16 hi/lo + fp16 copy   (4096 blocks)
//   y=1: zero M^T accum + row sums           (1056 blocks)
//   y=2: weight prep (Wq/Wk native split, Wv^T split)  (3072 blocks)
// ---------------------------------------------------------------------------
__global__ void prep_all(const float* __restrict__ x,
                         const float* __restrict__ Wq, const float* __restrict__ Wk,
                         const float* __restrict__ Wv,
                         bf16* __restrict__ xh, bf16* __restrict__ xl,
                         __half* __restrict__ xf,
                         float* __restrict__ Mt, float* __restrict__ s,
                         bf16* __restrict__ wnh, bf16* __restrict__ wnl,
                         bf16* __restrict__ wvth, bf16* __restrict__ wvtl)
{
    const int job = blockIdx.y;
    const int gx  = blockIdx.x * blockDim.x + threadIdx.x;
    if (job == 0) {                       // split x (float4 granularity)
        if (gx >= ROWS * DIM / 4) return;
        float4 v = ((const float4*)x)[gx];
        bf16 h0 = __float2bfloat16(v.x), h1 = __float2bfloat16(v.y);
        bf16 h2 = __float2bfloat16(v.z), h3 = __float2bfloat16(v.w);
        __nv_bfloat162 hp0, hp1, lp0, lp1;
        hp0.x = h0; hp0.y = h1; hp1.x = h2; hp1.y = h3;
        lp0.x = __float2bfloat16(v.x - __bfloat162float(h0));
        lp0.y = __float2bfloat16(v.y - __bfloat162float(h1));
        lp1.x = __float2bfloat16(v.z - __bfloat162float(h2));
        lp1.y = __float2bfloat16(v.w - __bfloat162float(h3));
        ((__nv_bfloat162*)xh)[gx * 2 + 0] = hp0;
        ((__nv_bfloat162*)xh)[gx * 2 + 1] = hp1;
        ((__nv_bfloat162*)xl)[gx * 2 + 0] = lp0;
        ((__nv_bfloat162*)xl)[gx * 2 + 1] = lp1;
        ((__half2*)xf)[gx * 2 + 0] = __halves2half2(__float2half_rn(v.x), __float2half_rn(v.y));
        ((__half2*)xf)[gx * 2 + 1] = __halves2half2(__float2half_rn(v.z), __float2half_rn(v.w));
    } else if (job == 1) {                // zero scratch
        if (gx < DD) Mt[gx] = 0.f;
        else if (gx < DD + ROWS) s[gx - DD] = 0.f;
    } else {                              // weight prep: gx in [0, 3*DD)
        if (gx >= 3 * DD) return;
        const int wsel = gx >> 18;        // /DD (DD = 262144 = 2^18)
        const int id   = gx & (DD - 1);
        if (wsel < 2) {
            float v = (wsel == 0) ? Wq[id] : Wk[id];
            bf16 hh = __float2bfloat16(v);
            wnh[(size_t)wsel * DD + id] = hh;
            wnl[(size_t)wsel * DD + id] = __float2bfloat16(v - __bfloat162float(hh));
        } else {
            int k = id >> 9, n = id & 511;
            float v = Wv[id];
            bf16 hh = __float2bfloat16(v);
            wvth[n * DIM + k] = hh;
            wvtl[n * DIM + k] = __float2bfloat16(v - __bfloat162float(hh));
        }
    }
}

// M^T fp32 -> bf16 split
__global__ void split_M(const float* __restrict__ Mt, bf16* __restrict__ h,
                        bf16* __restrict__ l)
{
    int i = blockIdx.x * blockDim.x + threadIdx.x;
    if (i >= DD) return;
    float v = Mt[i];
    bf16 hh = __float2bfloat16(v);
    h[i] = hh;
    l[i] = __float2bfloat16(v - __bfloat162float(hh));
}

// ---------------------------------------------------------------------------
extern "C" void kernel_launch(void* const* d_in, const int* in_sizes, int n_in,
                              void* d_out, int out_size)
{
    const float* x  = (const float*)d_in[0];
    const float* Wq = (const float*)d_in[1];
    const float* Wk = (const float*)d_in[2];
    const float* Wv = (const float*)d_in[3];
    float* out = (float*)d_out;

    bf16 *xh, *xl, *wnh, *wnl, *wvth, *wvtl, *Mth, *Mtl;
    __half *xf, *Yh, *Vth, *Ph;
    float *Mt, *sum;
    cudaGetSymbolAddress((void**)&xh,   g_xh);   cudaGetSymbolAddress((void**)&xl,   g_xl);
    cudaGetSymbolAddress((void**)&xf,   g_xf);
    cudaGetSymbolAddress((void**)&wnh,  g_wnh);  cudaGetSymbolAddress((void**)&wnl,  g_wnl);
    cudaGetSymbolAddress((void**)&wvth, g_wvth); cudaGetSymbolAddress((void**)&wvtl, g_wvtl);
    cudaGetSymbolAddress((void**)&Mt,   g_Mt);
    cudaGetSymbolAddress((void**)&Mth,  g_Mth);  cudaGetSymbolAddress((void**)&Mtl,  g_Mtl);
    cudaGetSymbolAddress((void**)&Yh,   g_Yh);
    cudaGetSymbolAddress((void**)&Vth,  g_Vth);
    cudaGetSymbolAddress((void**)&Ph,   g_Ph);
    cudaGetSymbolAddress((void**)&sum,  g_sum);

    const int SMEM3 = 2 * 4 * ARR;   // 3-term, 2 stages (81920)
    const int SMEM1 = 3 * 2 * ARR;   // 1-term, 3 stages (61440)
    cudaFuncSetAttribute(mma_gemm<5>, cudaFuncAttributeMaxDynamicSharedMemorySize, SMEM3);
    cudaFuncSetAttribute(mma_gemm<0>, cudaFuncAttributeMaxDynamicSharedMemorySize, SMEM3);
    cudaFuncSetAttribute(mma_gemm<4>, cudaFuncAttributeMaxDynamicSharedMemorySize, SMEM1);
    cudaFuncSetAttribute(mma_gemm<1>, cudaFuncAttributeMaxDynamicSharedMemorySize, SMEM1);

    const float inv_sqrt_d = 0.04419417382415922f;  // 1/sqrt(512)

    // 0) merged prep (split x | zero scratch | weight prep) — one launch
    {
        dim3 g(4096, 3);   // y=0 needs 4096 blocks; y=1/2 early-exit beyond range
        prep_all<<<g, 256>>>(x, Wq, Wk, Wv, xh, xl, xf, Mt, sum,
                             wnh, wnl, wvth, wvtl);
    }

    // 1) M^T = Wk · Wq^T, split-K over 8 (K=64 each), fp32 atomic accumulate
    {
        dim3 g(4, 4, 8);
        mma_gemm<5><<<g, 256, SMEM3>>>(
            (const uint16_t*)(wnh + DD), (const uint16_t*)(wnl + DD),  // A = Wk
            (const uint16_t*)wnh, (const uint16_t*)wnl,                 // B = Wq
            nullptr, nullptr,
            64, DIM, 0, 0,
            1.f, nullptr, nullptr, Mt, 0, DIM, nullptr, nullptr);
    }
    split_M<<<(DD + 255) / 256, 256>>>(Mt, Mth, Mtl);

    // 2) projections: z=0 -> y = x·M^T^T (fp16), z=1 -> V^T (fp16)
    {
        dim3 g(ROWS / 128, DIM / 128, 2);   // (64, 4, 2)
        mma_gemm<0><<<g, 256, SMEM3>>>(
            (const uint16_t*)xh, (const uint16_t*)xl,
            (const uint16_t*)Mth, (const uint16_t*)Mtl,
            (const uint16_t*)wvth, (const uint16_t*)wvtl,
            DIM, DIM, 0, 0,
            1.f, nullptr, nullptr, nullptr, 0, DIM, Yh, Vth);
    }

    // 3) fused scores + softmax-exp: P = exp(y·x^T/sqrt(d))  (fp16 1-term)
    {
        dim3 g(SEQ / 128, SEQ / 128, BATCH);
        mma_gemm<4><<<g, 256, SMEM1>>>(
            (const uint16_t*)Yh, nullptr, (const uint16_t*)xf, nullptr,
            nullptr, nullptr,
            DIM, DIM, (size_t)SEQ * DIM, (size_t)SEQ * DIM,
            inv_sqrt_d, nullptr, sum, nullptr, 0, 0, Ph, nullptr);
    }

    // 4) context = diag(1/rowsum) * (P @ V) — invert folded into epilogue
    {
        dim3 g(DIM / 128, SEQ / 128, BATCH);
        mma_gemm<1><<<g, 256, SMEM1>>>(
            (const uint16_t*)Ph, nullptr, (const uint16_t*)Vth, nullptr,
            nullptr, nullptr,
            SEQ, SEQ, (size_t)SEQ * SEQ, (size_t)DIM * SEQ,
            1.f, sum, nullptr, out, (size_t)SEQ * DIM, DIM, nullptr, nullptr);
    }
}

// round 16
// speedup vs baseline: 1.3062x; 1.0101x over previous
#include <cuda_runtime.h>
#include <cuda_bf16.h>
#include <cuda_fp16.h>
#include <math.h>
#include <stdint.h>

// Problem constants
#define BATCH 2
#define SEQ   4096
#define DIM   512
#define ROWS  (BATCH * SEQ)          // 8192
#define DD    (DIM * DIM)

typedef __nv_bfloat16 bf16;

// ---------------------------------------------------------------------------
// Device scratch (static globals — no allocations)
// ---------------------------------------------------------------------------
__device__ bf16   g_xh[ROWS * DIM],  g_xl[ROWS * DIM];   // x bf16 split
__device__ __half g_xf[ROWS * DIM];                       // x fp16 (scores B)
__device__ bf16   g_wnh[2 * DD], g_wnl[2 * DD];           // Wq(0), Wk(1) native split
__device__ bf16   g_wvth[DD], g_wvtl[DD];                 // Wv^T split
__device__ float  g_Mt[DD];                               // M^T fp32 accum
__device__ bf16   g_Mth[DD], g_Mtl[DD];                   // M^T bf16 split
__device__ __half g_Yh[ROWS * DIM];                       // y = x·M fp16
__device__ __half g_Vth[(size_t)BATCH * DIM * SEQ];       // V^T fp16 [b][d][s]
__device__ __half g_Ph[(size_t)BATCH * SEQ * SEQ];        // P fp16
__device__ float  g_sum[ROWS];                            // exp row sums (atomic)

// ---------------------------------------------------------------------------
// helpers (baseline sm_80+ PTX only — NO tcgen05 / 'a'-gated features)
// ---------------------------------------------------------------------------
__device__ __forceinline__ uint32_t smem_u32(const void* p) {
    uint32_t a;
    asm("{ .reg .u64 t; cvta.to.shared.u64 t, %1; cvt.u32.u64 %0, t; }" : "=r"(a) : "l"(p));
    return a;
}
#define CP16(dst, src) \
    asm volatile("cp.async.cg.shared.global [%0], [%1], 16;" :: "r"(dst), "l"(src))
#define CP_COMMIT() asm volatile("cp.async.commit_group;" ::: "memory")
#define CP_WAIT2()  asm volatile("cp.async.wait_group 2;" ::: "memory")
#define CP_WAIT1()  asm volatile("cp.async.wait_group 1;" ::: "memory")
#define CP_WAIT0()  asm volatile("cp.async.wait_group 0;" ::: "memory")

__device__ __forceinline__ void ldm_x4(uint32_t* r, uint32_t addr) {
    asm volatile("ldmatrix.sync.aligned.m8n8.x4.shared.b16 {%0,%1,%2,%3}, [%4];"
        : "=r"(r[0]), "=r"(r[1]), "=r"(r[2]), "=r"(r[3]) : "r"(addr));
}
__device__ __forceinline__ void mma_bf16(float* c, const uint32_t* a, const uint32_t* b) {
    asm volatile(
        "mma.sync.aligned.m16n8k16.row.col.f32.bf16.bf16.f32 "
        "{%0,%1,%2,%3}, {%4,%5,%6,%7}, {%8,%9}, {%0,%1,%2,%3};"
        : "+f"(c[0]), "+f"(c[1]), "+f"(c[2]), "+f"(c[3])
        : "r"(a[0]), "r"(a[1]), "r"(a[2]), "r"(a[3]), "r"(b[0]), "r"(b[1]));
}
__device__ __forceinline__ void mma_f16(float* c, const uint32_t* a, const uint32_t* b) {
    asm volatile(
        "mma.sync.aligned.m16n8k16.row.col.f32.f16.f16.f32 "
        "{%0,%1,%2,%3}, {%4,%5,%6,%7}, {%8,%9}, {%0,%1,%2,%3};"
        : "+f"(c[0]), "+f"(c[1]), "+f"(c[2]), "+f"(c[3])
        : "r"(a[0]), "r"(a[1]), "r"(a[2]), "r"(a[3]), "r"(b[0]), "r"(b[1]));
}
__device__ __forceinline__ void store2_h(__half* o, float a, float b) {
    *(__half2*)o = __halves2half2(__float2half_rn(a), __float2half_rn(b));
}

// smem: per-array 128 rows x 80 bytes (proven conflict-free layout)
#define ARR   10240

// ---------------------------------------------------------------------------
// NT GEMM via mma.sync: C[128x128] = sum_k A[m,k]*B[n,k], KC=32.
// ALL modes: __launch_bounds__(256, 2) — 128 regs/thread is a hard floor
// for the 64-accumulator tile (R12 lesson: (256,3) spills and regresses).
// MODE 5 (bf16 3-term, 2-stage): M^T = Wk·Wq^T, split-K over z,
//        fp32 atomicAdd into outF [512,512].
// MODE 0 (bf16 3-term, 2-stage): projections.
//        z=0 -> y (outH fp16): A=x split, B=M^T split
//        z=1 -> V^T (outH3 fp16, [b][d][s]): A=Wv^T split (Ch/Cl), B=x split
// MODE 4 (fp16 1-term, 4-stage, 1 barrier/chunk): scores, exp + atomic sums
// MODE 1 (fp16 1-term, 4-stage, 1 barrier/chunk): context,
//        outF = val / rowsum[z*SEQ+row]   (invert folded into epilogue)
// ---------------------------------------------------------------------------
template <int MODE>
__global__ __launch_bounds__(256, 2)
void mma_gemm(const uint16_t* __restrict__ Ah, const uint16_t* __restrict__ Al,
              const uint16_t* __restrict__ Bh, const uint16_t* __restrict__ Bl,
              const uint16_t* __restrict__ Ch, const uint16_t* __restrict__ Cl,
              int K, int ld, size_t strideA, size_t strideB,
              float alpha, const float* __restrict__ rowsum, float* gsum,
              float* __restrict__ outF, size_t strideOut, int ldOut,
              __half* __restrict__ outH, __half* __restrict__ outH3)
{
    constexpr bool T3   = (MODE == 0 || MODE == 5);   // 3-term bf16 split
    constexpr int  NARR = T3 ? 4 : 2;
    constexpr int  STG  = NARR * ARR;
    constexpr int  OFFB = T3 ? 2 * ARR : ARR;         // Bh offset within stage

    extern __shared__ char smem[];
    const uint32_t sb = smem_u32(smem);
    const int tid  = threadIdx.x;
    const int lane = tid & 31;
    const int wid  = tid >> 5;
    const int wm   = wid & 1;         // 2 warps along M (64 rows each)
    const int wn   = wid >> 1;        // 4 warps along N (32 cols each)
    const int z  = blockIdx.z;

    int m0, n0;
    const uint16_t *aH, *aL = nullptr, *bH, *bL = nullptr;
    if (MODE == 5) {                  // split-K: z selects K window
        m0 = blockIdx.y * 128;
        n0 = blockIdx.x * 128;
        const int koff = z * 64;
        aH = Ah + (size_t)m0 * ld + koff;
        aL = Al + (size_t)m0 * ld + koff;
        bH = Bh + (size_t)n0 * ld + koff;
        bL = Bl + (size_t)n0 * ld + koff;
    } else if (MODE == 0) {
        if (z == 0) {      // y: m over ROWS (bx), n over DIM (by)
            m0 = blockIdx.x * 128;
            n0 = blockIdx.y * 128;
            aH = Ah + (size_t)m0 * ld;          // x hi
            aL = Al + (size_t)m0 * ld;          // x lo
            bH = Bh + (size_t)n0 * ld;          // M^T hi
            bL = Bl + (size_t)n0 * ld;          // M^T lo
        } else {           // V: m over DIM (by), n over ROWS (bx)
            m0 = blockIdx.y * 128;
            n0 = blockIdx.x * 128;
            aH = Ch + (size_t)m0 * ld;          // Wv^T hi
            aL = Cl + (size_t)m0 * ld;          // Wv^T lo
            bH = Ah + (size_t)n0 * ld;          // x hi
            bL = Al + (size_t)n0 * ld;          // x lo
        }
    } else {
        m0 = blockIdx.y * 128;
        n0 = blockIdx.x * 128;
        aH = Ah + z * strideA + (size_t)m0 * ld;
        bH = Bh + z * strideB + (size_t)n0 * ld;
    }

    float acc[4][4][4];
#pragma unroll
    for (int i = 0; i < 4; i++)
#pragma unroll
        for (int j = 0; j < 4; j++)
#pragma unroll
            for (int q = 0; q < 4; q++) acc[i][j][q] = 0.f;

    const int nc = K >> 5;   // 32-wide k chunks

    auto load_stage = [&](int s, int k0) {
        const uint32_t base = sb + s * STG;
#pragma unroll
        for (int i = 0; i < 2; i++) {
            const int c   = tid + i * 256;
            const int row = c >> 2, kc = c & 3;
            const uint32_t doff = (uint32_t)(row * 80 + kc * 16);
            const size_t   soff = (size_t)row * ld + k0 + kc * 8;
            CP16(base + doff, (const void*)(aH + soff));
            CP16(base + OFFB + doff, (const void*)(bH + soff));
            if (T3) {
                CP16(base + 1 * ARR + doff, (const void*)(aL + soff));
                CP16(base + 3 * ARR + doff, (const void*)(bL + soff));
            }
        }
    };

    auto compute_chunk = [&](uint32_t s0) {
#pragma unroll
        for (int ks = 0; ks < 2; ks++) {
            uint32_t ah[4][4], al[4][4];
#pragma unroll
            for (int mi = 0; mi < 4; mi++) {
                const uint32_t ad = s0 +
                    (uint32_t)((wm * 64 + mi * 16 + (lane & 15)) * 80 + ks * 32 + (lane >> 4) * 16);
                ldm_x4(ah[mi], ad);
                if (T3) ldm_x4(al[mi], ad + ARR);
            }
#pragma unroll
            for (int bi = 0; bi < 2; bi++) {
                const uint32_t bd = s0 + OFFB +
                    (uint32_t)((wn * 32 + bi * 16 + (lane & 15)) * 80 + ks * 32 + (lane >> 4) * 16);
                uint32_t bh[4], bl[4];
                ldm_x4(bh, bd);
                if (T3) ldm_x4(bl, bd + ARR);
#pragma unroll
                for (int n2 = 0; n2 < 2; n2++) {
                    const int ni = bi * 2 + n2;
                    uint32_t bbh[2] = { bh[n2], bh[2 + n2] };
                    if (T3) {
                        uint32_t bbl[2] = { bl[n2], bl[2 + n2] };
#pragma unroll
                        for (int mi = 0; mi < 4; mi++) mma_bf16(acc[mi][ni], ah[mi], bbh);  // hh
#pragma unroll
                        for (int mi = 0; mi < 4; mi++) mma_bf16(acc[mi][ni], al[mi], bbh);  // lh
#pragma unroll
                        for (int mi = 0; mi < 4; mi++) mma_bf16(acc[mi][ni], ah[mi], bbl);  // hl
                    } else {
#pragma unroll
                        for (int mi = 0; mi < 4; mi++) mma_f16(acc[mi][ni], ah[mi], bbh);   // hh
                    }
                }
            }
        }
    };

    if (T3) {
        // 2-stage double buffer: two barriers per chunk (write hits the
        // stage read last iteration — trailing barrier is load-bearing).
        load_stage(0, 0);
        CP_COMMIT();
        for (int c = 0; c < nc; c++) {
            if (c + 1 < nc) {
                load_stage((c + 1) & 1, (c + 1) << 5);
                CP_COMMIT();
                CP_WAIT1();
            } else {
                CP_WAIT0();
            }
            __syncthreads();
            compute_chunk(sb + (c & 1) * STG);
            __syncthreads();
        }
    } else {
        // 4-stage: ONE barrier per chunk, TWO loads in flight during compute.
        // Load for c+3 targets stage (c+3)&3 == (c-1)&3, whose readers all
        // passed the barrier at iteration c — safe.
        load_stage(0, 0);
        CP_COMMIT();
        load_stage(1, 32);
        CP_COMMIT();
        load_stage(2, 64);
        CP_COMMIT();
        for (int c = 0; c < nc; c++) {
            if      (c + 2 < nc) CP_WAIT2();
            else if (c + 1 < nc) CP_WAIT1();
            else                 CP_WAIT0();
            __syncthreads();
            if (c + 3 < nc) {
                load_stage((c + 3) & 3, (c + 3) << 5);
                CP_COMMIT();
            }
            compute_chunk(sb + (c & 3) * STG);
        }
    }

    // ---- epilogue ----
    const int r  = lane >> 2;
    const int cq = (lane & 3) * 2;
#pragma unroll
    for (int mi = 0; mi < 4; mi++) {
        const int row0 = m0 + wm * 64 + mi * 16 + r;   // second half: row0+8
        float rs0 = 0.f, rs1 = 0.f;
        float is0 = 0.f, is1 = 0.f;
        if (MODE == 1) {               // invert folded here
            is0 = 1.0f / rowsum[z * SEQ + row0];
            is1 = 1.0f / rowsum[z * SEQ + row0 + 8];
        }
#pragma unroll
        for (int ni = 0; ni < 4; ni++) {
            const int col = n0 + wn * 32 + ni * 8 + cq;
            float v00 = acc[mi][ni][0], v01 = acc[mi][ni][1];
            float v10 = acc[mi][ni][2], v11 = acc[mi][ni][3];
            if (MODE == 5) {           // split-K accumulate into M^T fp32
                atomicAdd(&outF[(size_t)row0 * DIM + col],     v00);
                atomicAdd(&outF[(size_t)row0 * DIM + col + 1], v01);
                atomicAdd(&outF[(size_t)(row0 + 8) * DIM + col],     v10);
                atomicAdd(&outF[(size_t)(row0 + 8) * DIM + col + 1], v11);
            } else if (MODE == 0) {
                if (z == 0) {
                    const size_t o0 = (size_t)row0 * ldOut + col;
                    const size_t o1 = (size_t)(row0 + 8) * ldOut + col;
                    store2_h(outH + o0, v00, v01);
                    store2_h(outH + o1, v10, v11);
                } else {   // V^T: rows=d, cols=(b,s)
                    const int b = col >> 12, s = col & 4095;
                    const size_t o0 = (size_t)b * DIM * SEQ + (size_t)row0 * SEQ + s;
                    const size_t o1 = o0 + (size_t)8 * SEQ;
                    store2_h(outH3 + o0, v00, v01);
                    store2_h(outH3 + o1, v10, v11);
                }
            } else if (MODE == 4) {    // scores: exp + fp16 + row sums
                float e00 = __expf(v00 * alpha), e01 = __expf(v01 * alpha);
                float e10 = __expf(v10 * alpha), e11 = __expf(v11 * alpha);
                rs0 += e00 + e01;
                rs1 += e10 + e11;
                const size_t base = (size_t)z * SEQ * SEQ;
                const size_t o0 = base + (size_t)row0 * SEQ + col;
                const size_t o1 = base + (size_t)(row0 + 8) * SEQ + col;
                store2_h(outH + o0, e00, e01);
                store2_h(outH + o1, e10, e11);
            } else {                   // MODE 1: context, normalized fp32 out
                float* o0 = outF + z * strideOut + (size_t)row0 * ldOut + col;
                float* o1 = outF + z * strideOut + (size_t)(row0 + 8) * ldOut + col;
                *(float2*)o0 = make_float2(v00 * is0, v01 * is0);
                *(float2*)o1 = make_float2(v10 * is1, v11 * is1);
            }
        }
        if (MODE == 4) {
            rs0 += __shfl_xor_sync(0xffffffffu, rs0, 1);
            rs0 += __shfl_xor_sync(0xffffffffu, rs0, 2);
            rs1 += __shfl_xor_sync(0xffffffffu, rs1, 1);
            rs1 += __shfl_xor_sync(0xffffffffu, rs1, 2);
            if ((lane & 3) == 0) {
                atomicAdd(&gsum[z * SEQ + row0], rs0);
                atomicAdd(&gsum[z * SEQ + row0 + 8], rs1);
            }
        }
    }
}

// ---------------------------------------------------------------------------
// merged prep kernel: blockIdx.y selects the job (all independent)
// ---------------------------------------------------------------------------
__global__ void prep_all(const float* __restrict__ x,
                         const float* __restrict__ Wq, const float* __restrict__ Wk,
                         const float* __restrict__ Wv,
                         bf16* __restrict__ xh, bf16* __restrict__ xl,
                         __half* __restrict__ xf,
                         float* __restrict__ Mt, float* __restrict__ s,
                         bf16* __restrict__ wnh, bf16* __restrict__ wnl,
                         bf16* __restrict__ wvth, bf16* __restrict__ wvtl)
{
    const int job = blockIdx.y;
    const int gx  = blockIdx.x * blockDim.x + threadIdx.x;
    if (job == 0) {                       // split x (float4 granularity)
        if (gx >= ROWS * DIM / 4) return;
        float4 v = ((const float4*)x)[gx];
        bf16 h0 = __float2bfloat16(v.x), h1 = __float2bfloat16(v.y);
        bf16 h2 = __float2bfloat16(v.z), h3 = __float2bfloat16(v.w);
        __nv_bfloat162 hp0, hp1, lp0, lp1;
        hp0.x = h0; hp0.y = h1; hp1.x = h2; hp1.y = h3;
        lp0.x = __float2bfloat16(v.x - __bfloat162float(h0));
        lp0.y = __float2bfloat16(v.y - __bfloat162float(h1));
        lp1.x = __float2bfloat16(v.z - __bfloat162float(h2));
        lp1.y = __float2bfloat16(v.w - __bfloat162float(h3));
        ((__nv_bfloat162*)xh)[gx * 2 + 0] = hp0;
        ((__nv_bfloat162*)xh)[gx * 2 + 1] = hp1;
        ((__nv_bfloat162*)xl)[gx * 2 + 0] = lp0;
        ((__nv_bfloat162*)xl)[gx * 2 + 1] = lp1;
        ((__half2*)xf)[gx * 2 + 0] = __halves2half2(__float2half_rn(v.x), __float2half_rn(v.y));
        ((__half2*)xf)[gx * 2 + 1] = __halves2half2(__float2half_rn(v.z), __float2half_rn(v.w));
    } else if (job == 1) {                // zero scratch
        if (gx < DD) Mt[gx] = 0.f;
        else if (gx < DD + ROWS) s[gx - DD] = 0.f;
    } else {                              // weight prep: gx in [0, 3*DD)
        if (gx >= 3 * DD) return;
        const int wsel = gx >> 18;        // /DD (DD = 262144 = 2^18)
        const int id   = gx & (DD - 1);
        if (wsel < 2) {
            float v = (wsel == 0) ? Wq[id] : Wk[id];
            bf16 hh = __float2bfloat16(v);
            wnh[(size_t)wsel * DD + id] = hh;
            wnl[(size_t)wsel * DD + id] = __float2bfloat16(v - __bfloat162float(hh));
        } else {
            int k = id >> 9, n = id & 511;
            float v = Wv[id];
            bf16 hh = __float2bfloat16(v);
            wvth[n * DIM + k] = hh;
            wvtl[n * DIM + k] = __float2bfloat16(v - __bfloat162float(hh));
        }
    }
}

// M^T fp32 -> bf16 split
__global__ void split_M(const float* __restrict__ Mt, bf16* __restrict__ h,
                        bf16* __restrict__ l)
{
    int i = blockIdx.x * blockDim.x + threadIdx.x;
    if (i >= DD) return;
    float v = Mt[i];
    bf16 hh = __float2bfloat16(v);
    h[i] = hh;
    l[i] = __float2bfloat16(v - __bfloat162float(hh));
}

// ---------------------------------------------------------------------------
extern "C" void kernel_launch(void* const* d_in, const int* in_sizes, int n_in,
                              void* d_out, int out_size)
{
    const float* x  = (const float*)d_in[0];
    const float* Wq = (const float*)d_in[1];
    const float* Wk = (const float*)d_in[2];
    const float* Wv = (const float*)d_in[3];
    float* out = (float*)d_out;

    bf16 *xh, *xl, *wnh, *wnl, *wvth, *wvtl, *Mth, *Mtl;
    __half *xf, *Yh, *Vth, *Ph;
    float *Mt, *sum;
    cudaGetSymbolAddress((void**)&xh,   g_xh);   cudaGetSymbolAddress((void**)&xl,   g_xl);
    cudaGetSymbolAddress((void**)&xf,   g_xf);
    cudaGetSymbolAddress((void**)&wnh,  g_wnh);  cudaGetSymbolAddress((void**)&wnl,  g_wnl);
    cudaGetSymbolAddress((void**)&wvth, g_wvth); cudaGetSymbolAddress((void**)&wvtl, g_wvtl);
    cudaGetSymbolAddress((void**)&Mt,   g_Mt);
    cudaGetSymbolAddress((void**)&Mth,  g_Mth);  cudaGetSymbolAddress((void**)&Mtl,  g_Mtl);
    cudaGetSymbolAddress((void**)&Yh,   g_Yh);
    cudaGetSymbolAddress((void**)&Vth,  g_Vth);
    cudaGetSymbolAddress((void**)&Ph,   g_Ph);
    cudaGetSymbolAddress((void**)&sum,  g_sum);

    const int SMEM3 = 2 * 4 * ARR;   // 3-term, 2 stages (81920)
    const int SMEM1 = 4 * 2 * ARR;   // 1-term, 4 stages (81920)
    cudaFuncSetAttribute(mma_gemm<5>, cudaFuncAttributeMaxDynamicSharedMemorySize, SMEM3);
    cudaFuncSetAttribute(mma_gemm<0>, cudaFuncAttributeMaxDynamicSharedMemorySize, SMEM3);
    cudaFuncSetAttribute(mma_gemm<4>, cudaFuncAttributeMaxDynamicSharedMemorySize, SMEM1);
    cudaFuncSetAttribute(mma_gemm<1>, cudaFuncAttributeMaxDynamicSharedMemorySize, SMEM1);

    const float inv_sqrt_d = 0.04419417382415922f;  // 1/sqrt(512)

    // 0) merged prep (split x | zero scratch | weight prep) — one launch
    {
        dim3 g(4096, 3);
        prep_all<<<g, 256>>>(x, Wq, Wk, Wv, xh, xl, xf, Mt, sum,
                             wnh, wnl, wvth, wvtl);
    }

    // 1) M^T = Wk · Wq^T, split-K over 8 (K=64 each), fp32 atomic accumulate
    {
        dim3 g(4, 4, 8);
        mma_gemm<5><<<g, 256, SMEM3>>>(
            (const uint16_t*)(wnh + DD), (const uint16_t*)(wnl + DD),  // A = Wk
            (const uint16_t*)wnh, (const uint16_t*)wnl,                 // B = Wq
            nullptr, nullptr,
            64, DIM, 0, 0,
            1.f, nullptr, nullptr, Mt, 0, DIM, nullptr, nullptr);
    }
    split_M<<<(DD + 255) / 256, 256>>>(Mt, Mth, Mtl);

    // 2) projections: z=0 -> y = x·M^T^T (fp16), z=1 -> V^T (fp16)
    {
        dim3 g(ROWS / 128, DIM / 128, 2);   // (64, 4, 2)
        mma_gemm<0><<<g, 256, SMEM3>>>(
            (const uint16_t*)xh, (const uint16_t*)xl,
            (const uint16_t*)Mth, (const uint16_t*)Mtl,
            (const uint16_t*)wvth, (const uint16_t*)wvtl,
            DIM, DIM, 0, 0,
            1.f, nullptr, nullptr, nullptr, 0, DIM, Yh, Vth);
    }

    // 3) fused scores + softmax-exp: P = exp(y·x^T/sqrt(d))  (fp16 1-term, 4-stage)
    {
        dim3 g(SEQ / 128, SEQ / 128, BATCH);
        mma_gemm<4><<<g, 256, SMEM1>>>(
            (const uint16_t*)Yh, nullptr, (const uint16_t*)xf, nullptr,
            nullptr, nullptr,
            DIM, DIM, (size_t)SEQ * DIM, (size_t)SEQ * DIM,
            inv_sqrt_d, nullptr, sum, nullptr, 0, 0, Ph, nullptr);
    }

    // 4) context = diag(1/rowsum) * (P @ V) — invert folded into epilogue
    {
        dim3 g(DIM / 128, SEQ / 128, BATCH);
        mma_gemm<1><<<g, 256, SMEM1>>>(
            (const uint16_t*)Ph, nullptr, (const uint16_t*)Vth, nullptr,
            nullptr, nullptr,
            SEQ, SEQ, (size_t)SEQ * SEQ, (size_t)DIM * SEQ,
            1.f, sum, nullptr, out, (size_t)SEQ * DIM, DIM, nullptr, nullptr);
    }
}

// round 17
// speedup vs baseline: 1.3989x; 1.0710x over previous
#include <cuda_runtime.h>
#include <cuda_bf16.h>
#include <cuda_fp16.h>
#include <math.h>
#include <stdint.h>

// Problem constants
#define BATCH 2
#define SEQ   4096
#define DIM   512
#define ROWS  (BATCH * SEQ)          // 8192
#define DD    (DIM * DIM)

typedef __nv_bfloat16 bf16;

// ---------------------------------------------------------------------------
// Device scratch (static globals — no allocations)
// ---------------------------------------------------------------------------
__device__ bf16   g_xh[ROWS * DIM],  g_xl[ROWS * DIM];   // x bf16 split
__device__ __half g_xf[ROWS * DIM];                       // x fp16 (scores B)
__device__ bf16   g_wnh[2 * DD], g_wnl[2 * DD];           // Wq(0), Wk(1) native split
__device__ bf16   g_wvth[DD], g_wvtl[DD];                 // Wv^T split
__device__ float  g_Mt[DD];                               // M^T fp32 accum
__device__ bf16   g_Mth[DD], g_Mtl[DD];                   // M^T bf16 split
__device__ __half g_Yh[ROWS * DIM];                       // y = x·M fp16
__device__ __half g_Vth[(size_t)BATCH * DIM * SEQ];       // V^T fp16 [b][d][s]
__device__ __half g_Ph[(size_t)BATCH * SEQ * SEQ];        // P fp16
__device__ float  g_sum[ROWS];                            // exp row sums (atomic)

// ---------------------------------------------------------------------------
// helpers (baseline sm_80+ PTX only — NO tcgen05 / 'a'-gated features)
// ---------------------------------------------------------------------------
__device__ __forceinline__ uint32_t smem_u32(const void* p) {
    uint32_t a;
    asm("{ .reg .u64 t; cvta.to.shared.u64 t, %1; cvt.u32.u64 %0, t; }" : "=r"(a) : "l"(p));
    return a;
}
#define CP16(dst, src) \
    asm volatile("cp.async.cg.shared.global [%0], [%1], 16;" :: "r"(dst), "l"(src))
#define CP_COMMIT() asm volatile("cp.async.commit_group;" ::: "memory")
#define CP_WAIT1()  asm volatile("cp.async.wait_group 1;" ::: "memory")
#define CP_WAIT0()  asm volatile("cp.async.wait_group 0;" ::: "memory")

__device__ __forceinline__ void ldm_x4(uint32_t* r, uint32_t addr) {
    asm volatile("ldmatrix.sync.aligned.m8n8.x4.shared.b16 {%0,%1,%2,%3}, [%4];"
        : "=r"(r[0]), "=r"(r[1]), "=r"(r[2]), "=r"(r[3]) : "r"(addr));
}
__device__ __forceinline__ void mma_bf16(float* c, const uint32_t* a, const uint32_t* b) {
    asm volatile(
        "mma.sync.aligned.m16n8k16.row.col.f32.bf16.bf16.f32 "
        "{%0,%1,%2,%3}, {%4,%5,%6,%7}, {%8,%9}, {%0,%1,%2,%3};"
        : "+f"(c[0]), "+f"(c[1]), "+f"(c[2]), "+f"(c[3])
        : "r"(a[0]), "r"(a[1]), "r"(a[2]), "r"(a[3]), "r"(b[0]), "r"(b[1]));
}
__device__ __forceinline__ void mma_f16(float* c, const uint32_t* a, const uint32_t* b) {
    asm volatile(
        "mma.sync.aligned.m16n8k16.row.col.f32.f16.f16.f32 "
        "{%0,%1,%2,%3}, {%4,%5,%6,%7}, {%8,%9}, {%0,%1,%2,%3};"
        : "+f"(c[0]), "+f"(c[1]), "+f"(c[2]), "+f"(c[3])
        : "r"(a[0]), "r"(a[1]), "r"(a[2]), "r"(a[3]), "r"(b[0]), "r"(b[1]));
}
__device__ __forceinline__ void store2_h(__half* o, float a, float b) {
    *(__half2*)o = __halves2half2(__float2half_rn(a), __float2half_rn(b));
}

// ---------------------------------------------------------------------------
// NT GEMM via mma.sync: C[128x128] = sum_k A[m,k]*B[n,k].
// ALL modes: __launch_bounds__(256, 2) — 128 regs/thread is a hard floor
// for the 64-accumulator tile (R12 lesson).
// T3 modes (0, 5): bf16 3-term, KC=32, 2-stage, PITCH=80 (proven).
// 1-term modes (4, 1): fp16, KC=64, 3-stage, PITCH=144, ONE barrier per
//   64-k chunk; compute body is the proven KC=32 body called twice.
// MODE 5: M^T = Wk·Wq^T, split-K over z, fp32 atomicAdd into outF.
// MODE 0: projections. z=0 -> y (outH fp16); z=1 -> V^T (outH3, [b][d][s]).
// MODE 4: scores, exp(val*alpha) -> fp16 + atomic row sums.
// MODE 1: context, outF = val / rowsum[z*SEQ+row].
// ---------------------------------------------------------------------------
template <int MODE>
__global__ __launch_bounds__(256, 2)
void mma_gemm(const uint16_t* __restrict__ Ah, const uint16_t* __restrict__ Al,
              const uint16_t* __restrict__ Bh, const uint16_t* __restrict__ Bl,
              const uint16_t* __restrict__ Ch, const uint16_t* __restrict__ Cl,
              int K, int ld, size_t strideA, size_t strideB,
              float alpha, const float* __restrict__ rowsum, float* gsum,
              float* __restrict__ outF, size_t strideOut, int ldOut,
              __half* __restrict__ outH, __half* __restrict__ outH3)
{
    constexpr bool T3    = (MODE == 0 || MODE == 5);   // 3-term bf16 split
    constexpr int  NARR  = T3 ? 4 : 2;
    constexpr int  PITCH = T3 ? 80 : 144;              // bytes per smem row
    constexpr int  ARRB  = 128 * PITCH;                // bytes per array
    constexpr int  STG   = NARR * ARRB;
    constexpr int  OFFB  = T3 ? 2 * ARRB : ARRB;       // Bh offset within stage
    constexpr int  KC    = T3 ? 32 : 64;               // k elems per stage

    extern __shared__ char smem[];
    const uint32_t sb = smem_u32(smem);
    const int tid  = threadIdx.x;
    const int lane = tid & 31;
    const int wid  = tid >> 5;
    const int wm   = wid & 1;         // 2 warps along M (64 rows each)
    const int wn   = wid >> 1;        // 4 warps along N (32 cols each)
    const int z  = blockIdx.z;

    int m0, n0;
    const uint16_t *aH, *aL = nullptr, *bH, *bL = nullptr;
    if (MODE == 5) {                  // split-K: z selects K window
        m0 = blockIdx.y * 128;
        n0 = blockIdx.x * 128;
        const int koff = z * 64;
        aH = Ah + (size_t)m0 * ld + koff;
        aL = Al + (size_t)m0 * ld + koff;
        bH = Bh + (size_t)n0 * ld + koff;
        bL = Bl + (size_t)n0 * ld + koff;
    } else if (MODE == 0) {
        if (z == 0) {      // y: m over ROWS (bx), n over DIM (by)
            m0 = blockIdx.x * 128;
            n0 = blockIdx.y * 128;
            aH = Ah + (size_t)m0 * ld;          // x hi
            aL = Al + (size_t)m0 * ld;          // x lo
            bH = Bh + (size_t)n0 * ld;          // M^T hi
            bL = Bl + (size_t)n0 * ld;          // M^T lo
        } else {           // V: m over DIM (by), n over ROWS (bx)
            m0 = blockIdx.y * 128;
            n0 = blockIdx.x * 128;
            aH = Ch + (size_t)m0 * ld;          // Wv^T hi
            aL = Cl + (size_t)m0 * ld;          // Wv^T lo
            bH = Ah + (size_t)n0 * ld;          // x hi
            bL = Al + (size_t)n0 * ld;          // x lo
        }
    } else {
        m0 = blockIdx.y * 128;
        n0 = blockIdx.x * 128;
        aH = Ah + z * strideA + (size_t)m0 * ld;
        bH = Bh + z * strideB + (size_t)n0 * ld;
    }

    float acc[4][4][4];
#pragma unroll
    for (int i = 0; i < 4; i++)
#pragma unroll
        for (int j = 0; j < 4; j++)
#pragma unroll
            for (int q = 0; q < 4; q++) acc[i][j][q] = 0.f;

    const int nc = K / KC;   // chunks

    auto load_stage = [&](int s, int k0) {
        const uint32_t base = sb + s * STG;
        if (T3) {
#pragma unroll
            for (int i = 0; i < 2; i++) {
                const int c   = tid + i * 256;        // 0..511
                const int row = c >> 2, kc = c & 3;
                const uint32_t doff = (uint32_t)(row * PITCH + kc * 16);
                const size_t   soff = (size_t)row * ld + k0 + kc * 8;
                CP16(base + doff, (const void*)(aH + soff));
                CP16(base + OFFB + doff, (const void*)(bH + soff));
                CP16(base + 1 * ARRB + doff, (const void*)(aL + soff));
                CP16(base + 3 * ARRB + doff, (const void*)(bL + soff));
            }
        } else {
#pragma unroll
            for (int i = 0; i < 4; i++) {
                const int c   = tid + i * 256;        // 0..1023
                const int row = c >> 3, kc = c & 7;
                const uint32_t doff = (uint32_t)(row * PITCH + kc * 16);
                const size_t   soff = (size_t)row * ld + k0 + kc * 8;
                CP16(base + doff, (const void*)(aH + soff));
                CP16(base + OFFB + doff, (const void*)(bH + soff));
            }
        }
    };

    // proven KC=32 compute body; kb = byte offset of the 32-elem sub-chunk
    auto compute_half = [&](uint32_t s0, int kb) {
#pragma unroll
        for (int ks = 0; ks < 2; ks++) {
            uint32_t ah[4][4], al[4][4];
#pragma unroll
            for (int mi = 0; mi < 4; mi++) {
                const uint32_t ad = s0 +
                    (uint32_t)((wm * 64 + mi * 16 + (lane & 15)) * PITCH + kb + ks * 32 + (lane >> 4) * 16);
                ldm_x4(ah[mi], ad);
                if (T3) ldm_x4(al[mi], ad + ARRB);
            }
#pragma unroll
            for (int bi = 0; bi < 2; bi++) {
                const uint32_t bd = s0 + OFFB +
                    (uint32_t)((wn * 32 + bi * 16 + (lane & 15)) * PITCH + kb + ks * 32 + (lane >> 4) * 16);
                uint32_t bh[4], bl[4];
                ldm_x4(bh, bd);
                if (T3) ldm_x4(bl, bd + ARRB);
#pragma unroll
                for (int n2 = 0; n2 < 2; n2++) {
                    const int ni = bi * 2 + n2;
                    uint32_t bbh[2] = { bh[n2], bh[2 + n2] };
                    if (T3) {
                        uint32_t bbl[2] = { bl[n2], bl[2 + n2] };
#pragma unroll
                        for (int mi = 0; mi < 4; mi++) mma_bf16(acc[mi][ni], ah[mi], bbh);  // hh
#pragma unroll
                        for (int mi = 0; mi < 4; mi++) mma_bf16(acc[mi][ni], al[mi], bbh);  // lh
#pragma unroll
                        for (int mi = 0; mi < 4; mi++) mma_bf16(acc[mi][ni], ah[mi], bbl);  // hl
                    } else {
#pragma unroll
                        for (int mi = 0; mi < 4; mi++) mma_f16(acc[mi][ni], ah[mi], bbh);   // hh
                    }
                }
            }
        }
    };

    if (T3) {
        // 2-stage double buffer (proven): two barriers per chunk.
        load_stage(0, 0);
        CP_COMMIT();
        for (int c = 0; c < nc; c++) {
            if (c + 1 < nc) {
                load_stage((c + 1) & 1, (c + 1) * KC);
                CP_COMMIT();
                CP_WAIT1();
            } else {
                CP_WAIT0();
            }
            __syncthreads();
            compute_half(sb + (c & 1) * STG, 0);
            __syncthreads();
        }
    } else {
        // 3-stage, KC=64: ONE barrier per chunk. Load for c+2 targets stage
        // (c+2)%3 = (c-1)%3, whose readers all passed the barrier at c — safe.
        load_stage(0, 0);
        CP_COMMIT();
        load_stage(1, KC);
        CP_COMMIT();
        for (int c = 0; c < nc; c++) {
            if (c + 1 < nc) CP_WAIT1();
            else            CP_WAIT0();
            __syncthreads();
            if (c + 2 < nc) {
                load_stage((c + 2) % 3, (c + 2) * KC);
                CP_COMMIT();
            }
            const uint32_t s0 = sb + (c % 3) * STG;
            compute_half(s0, 0);
            compute_half(s0, 64);
        }
    }

    // ---- epilogue ----
    const int r  = lane >> 2;
    const int cq = (lane & 3) * 2;
#pragma unroll
    for (int mi = 0; mi < 4; mi++) {
        const int row0 = m0 + wm * 64 + mi * 16 + r;   // second half: row0+8
        float rs0 = 0.f, rs1 = 0.f;
        float is0 = 0.f, is1 = 0.f;
        if (MODE == 1) {               // invert folded here
            is0 = 1.0f / rowsum[z * SEQ + row0];
            is1 = 1.0f / rowsum[z * SEQ + row0 + 8];
        }
#pragma unroll
        for (int ni = 0; ni < 4; ni++) {
            const int col = n0 + wn * 32 + ni * 8 + cq;
            float v00 = acc[mi][ni][0], v01 = acc[mi][ni][1];
            float v10 = acc[mi][ni][2], v11 = acc[mi][ni][3];
            if (MODE == 5) {           // split-K accumulate into M^T fp32
                atomicAdd(&outF[(size_t)row0 * DIM + col],     v00);
                atomicAdd(&outF[(size_t)row0 * DIM + col + 1], v01);
                atomicAdd(&outF[(size_t)(row0 + 8) * DIM + col],     v10);
                atomicAdd(&outF[(size_t)(row0 + 8) * DIM + col + 1], v11);
            } else if (MODE == 0) {
                if (z == 0) {
                    const size_t o0 = (size_t)row0 * ldOut + col;
                    const size_t o1 = (size_t)(row0 + 8) * ldOut + col;
                    store2_h(outH + o0, v00, v01);
                    store2_h(outH + o1, v10, v11);
                } else {   // V^T: rows=d, cols=(b,s)
                    const int b = col >> 12, s = col & 4095;
                    const size_t o0 = (size_t)b * DIM * SEQ + (size_t)row0 * SEQ + s;
                    const size_t o1 = o0 + (size_t)8 * SEQ;
                    store2_h(outH3 + o0, v00, v01);
                    store2_h(outH3 + o1, v10, v11);
                }
            } else if (MODE == 4) {    // scores: exp + fp16 + row sums
                float e00 = __expf(v00 * alpha), e01 = __expf(v01 * alpha);
                float e10 = __expf(v10 * alpha), e11 = __expf(v11 * alpha);
                rs0 += e00 + e01;
                rs1 += e10 + e11;
                const size_t base = (size_t)z * SEQ * SEQ;
                const size_t o0 = base + (size_t)row0 * SEQ + col;
                const size_t o1 = base + (size_t)(row0 + 8) * SEQ + col;
                store2_h(outH + o0, e00, e01);
                store2_h(outH + o1, e10, e11);
            } else {                   // MODE 1: context, normalized fp32 out
                float* o0 = outF + z * strideOut + (size_t)row0 * ldOut + col;
                float* o1 = outF + z * strideOut + (size_t)(row0 + 8) * ldOut + col;
                *(float2*)o0 = make_float2(v00 * is0, v01 * is0);
                *(float2*)o1 = make_float2(v10 * is1, v11 * is1);
            }
        }
        if (MODE == 4) {
            rs0 += __shfl_xor_sync(0xffffffffu, rs0, 1);
            rs0 += __shfl_xor_sync(0xffffffffu, rs0, 2);
            rs1 += __shfl_xor_sync(0xffffffffu, rs1, 1);
            rs1 += __shfl_xor_sync(0xffffffffu, rs1, 2);
            if ((lane & 3) == 0) {
                atomicAdd(&gsum[z * SEQ + row0], rs0);
                atomicAdd(&gsum[z * SEQ + row0 + 8], rs1);
            }
        }
    }
}

// ---------------------------------------------------------------------------
// merged prep kernel: blockIdx.y selects the job (all independent)
// ---------------------------------------------------------------------------
__global__ void prep_all(const float* __restrict__ x,
                         const float* __restrict__ Wq, const float* __restrict__ Wk,
                         const float* __restrict__ Wv,
                         bf16* __restrict__ xh, bf16* __restrict__ xl,
                         __half* __restrict__ xf,
                         float* __restrict__ Mt, float* __restrict__ s,
                         bf16* __restrict__ wnh, bf16* __restrict__ wnl,
                         bf16* __restrict__ wvth, bf16* __restrict__ wvtl)
{
    const int job = blockIdx.y;
    const int gx  = blockIdx.x * blockDim.x + threadIdx.x;
    if (job == 0) {                       // split x (float4 granularity)
        if (gx >= ROWS * DIM / 4) return;
        float4 v = ((const float4*)x)[gx];
        bf16 h0 = __float2bfloat16(v.x), h1 = __float2bfloat16(v.y);
        bf16 h2 = __float2bfloat16(v.z), h3 = __float2bfloat16(v.w);
        __nv_bfloat162 hp0, hp1, lp0, lp1;
        hp0.x = h0; hp0.y = h1; hp1.x = h2; hp1.y = h3;
        lp0.x = __float2bfloat16(v.x - __bfloat162float(h0));
        lp0.y = __float2bfloat16(v.y - __bfloat162float(h1));
        lp1.x = __float2bfloat16(v.z - __bfloat162float(h2));
        lp1.y = __float2bfloat16(v.w - __bfloat162float(h3));
        ((__nv_bfloat162*)xh)[gx * 2 + 0] = hp0;
        ((__nv_bfloat162*)xh)[gx * 2 + 1] = hp1;
        ((__nv_bfloat162*)xl)[gx * 2 + 0] = lp0;
        ((__nv_bfloat162*)xl)[gx * 2 + 1] = lp1;
        ((__half2*)xf)[gx * 2 + 0] = __halves2half2(__float2half_rn(v.x), __float2half_rn(v.y));
        ((__half2*)xf)[gx * 2 + 1] = __halves2half2(__float2half_rn(v.z), __float2half_rn(v.w));
    } else if (job == 1) {                // zero scratch
        if (gx < DD) Mt[gx] = 0.f;
        else if (gx < DD + ROWS) s[gx - DD] = 0.f;
    } else {                              // weight prep: gx in [0, 3*DD)
        if (gx >= 3 * DD) return;
        const int wsel = gx >> 18;        // /DD (DD = 262144 = 2^18)
        const int id   = gx & (DD - 1);
        if (wsel < 2) {
            float v = (wsel == 0) ? Wq[id] : Wk[id];
            bf16 hh = __float2bfloat16(v);
            wnh[(size_t)wsel * DD + id] = hh;
            wnl[(size_t)wsel * DD + id] = __float2bfloat16(v - __bfloat162float(hh));
        } else {
            int k = id >> 9, n = id & 511;
            float v = Wv[id];
            bf16 hh = __float2bfloat16(v);
            wvth[n * DIM + k] = hh;
            wvtl[n * DIM + k] = __float2bfloat16(v - __bfloat162float(hh));
        }
    }
}

// M^T fp32 -> bf16 split
__global__ void split_M(const float* __restrict__ Mt, bf16* __restrict__ h,
                        bf16* __restrict__ l)
{
    int i = blockIdx.x * blockDim.x + threadIdx.x;
    if (i >= DD) return;
    float v = Mt[i];
    bf16 hh = __float2bfloat16(v);
    h[i] = hh;
    l[i] = __float2bfloat16(v - __bfloat162float(hh));
}

// ---------------------------------------------------------------------------
extern "C" void kernel_launch(void* const* d_in, const int* in_sizes, int n_in,
                              void* d_out, int out_size)
{
    const float* x  = (const float*)d_in[0];
    const float* Wq = (const float*)d_in[1];
    const float* Wk = (const float*)d_in[2];
    const float* Wv = (const float*)d_in[3];
    float* out = (float*)d_out;

    bf16 *xh, *xl, *wnh, *wnl, *wvth, *wvtl, *Mth, *Mtl;
    __half *xf, *Yh, *Vth, *Ph;
    float *Mt, *sum;
    cudaGetSymbolAddress((void**)&xh,   g_xh);   cudaGetSymbolAddress((void**)&xl,   g_xl);
    cudaGetSymbolAddress((void**)&xf,   g_xf);
    cudaGetSymbolAddress((void**)&wnh,  g_wnh);  cudaGetSymbolAddress((void**)&wnl,  g_wnl);
    cudaGetSymbolAddress((void**)&wvth, g_wvth); cudaGetSymbolAddress((void**)&wvtl, g_wvtl);
    cudaGetSymbolAddress((void**)&Mt,   g_Mt);
    cudaGetSymbolAddress((void**)&Mth,  g_Mth);  cudaGetSymbolAddress((void**)&Mtl,  g_Mtl);
    cudaGetSymbolAddress((void**)&Yh,   g_Yh);
    cudaGetSymbolAddress((void**)&Vth,  g_Vth);
    cudaGetSymbolAddress((void**)&Ph,   g_Ph);
    cudaGetSymbolAddress((void**)&sum,  g_sum);

    const int SMEM3 = 2 * 4 * (128 * 80);    // 3-term, 2 stages (81920)
    const int SMEM1 = 3 * 2 * (128 * 144);   // 1-term, 3 stages KC=64 (110592)
    cudaFuncSetAttribute(mma_gemm<5>, cudaFuncAttributeMaxDynamicSharedMemorySize, SMEM3);
    cudaFuncSetAttribute(mma_gemm<0>, cudaFuncAttributeMaxDynamicSharedMemorySize, SMEM3);
    cudaFuncSetAttribute(mma_gemm<4>, cudaFuncAttributeMaxDynamicSharedMemorySize, SMEM1);
    cudaFuncSetAttribute(mma_gemm<1>, cudaFuncAttributeMaxDynamicSharedMemorySize, SMEM1);

    const float inv_sqrt_d = 0.04419417382415922f;  // 1/sqrt(512)

    // 0) merged prep (split x | zero scratch | weight prep) — one launch
    {
        dim3 g(4096, 3);
        prep_all<<<g, 256>>>(x, Wq, Wk, Wv, xh, xl, xf, Mt, sum,
                             wnh, wnl, wvth, wvtl);
    }

    // 1) M^T = Wk · Wq^T, split-K over 8 (K=64 each), fp32 atomic accumulate
    {
        dim3 g(4, 4, 8);
        mma_gemm<5><<<g, 256, SMEM3>>>(
            (const uint16_t*)(wnh + DD), (const uint16_t*)(wnl + DD),  // A = Wk
            (const uint16_t*)wnh, (const uint16_t*)wnl,                 // B = Wq
            nullptr, nullptr,
            64, DIM, 0, 0,
            1.f, nullptr, nullptr, Mt, 0, DIM, nullptr, nullptr);
    }
    split_M<<<(DD + 255) / 256, 256>>>(Mt, Mth, Mtl);

    // 2) projections: z=0 -> y = x·M^T^T (fp16), z=1 -> V^T (fp16)
    {
        dim3 g(ROWS / 128, DIM / 128, 2);   // (64, 4, 2)
        mma_gemm<0><<<g, 256, SMEM3>>>(
            (const uint16_t*)xh, (const uint16_t*)xl,
            (const uint16_t*)Mth, (const uint16_t*)Mtl,
            (const uint16_t*)wvth, (const uint16_t*)wvtl,
            DIM, DIM, 0, 0,
            1.f, nullptr, nullptr, nullptr, 0, DIM, Yh, Vth);
    }

    // 3) fused scores + softmax-exp: P = exp(y·x^T/sqrt(d))  (fp16, KC=64, 3-stage)
    {
        dim3 g(SEQ / 128, SEQ / 128, BATCH);
        mma_gemm<4><<<g, 256, SMEM1>>>(
            (const uint16_t*)Yh, nullptr, (const uint16_t*)xf, nullptr,
            nullptr, nullptr,
            DIM, DIM, (size_t)SEQ * DIM, (size_t)SEQ * DIM,
            inv_sqrt_d, nullptr, sum, nullptr, 0, 0, Ph, nullptr);
    }

    // 4) context = diag(1/rowsum) * (P @ V) — invert folded into epilogue
    {
        dim3 g(DIM / 128, SEQ / 128, BATCH);
        mma_gemm<1><<<g, 256, SMEM1>>>(
            (const uint16_t*)Ph, nullptr, (const uint16_t*)Vth, nullptr,
            nullptr, nullptr,
            SEQ, SEQ, (size_t)SEQ * SEQ, (size_t)DIM * SEQ,
            1.f, sum, nullptr, out, (size_t)SEQ * DIM, DIM, nullptr, nullptr);
    }
}